// round 6
// baseline (speedup 1.0000x reference)
#include <cuda_runtime.h>
#include <cuda_bf16.h>
#include <math.h>
#include <float.h>
#include <stdint.h>

// ---------------------------------------------------------------------------
// DeepRare, persistent kernel with WORK-STEALING phases:
//  P1 minmax (4608 units) -> P2 hist+gidx (4608, L2-hot) -> P3 stats ->
//  P4 proc (439 units) -> P5 all-layer pminmax -> P6 resize (1125) -> P7 final
// ---------------------------------------------------------------------------

#define NCH 1472
#define GIDX_TOTAL 28108800
#define NB 740          // 148 SMs x 5 blocks (fits 152-SM GB300 too)

__device__ unsigned g_bar;
__device__ unsigned g_ctr[4];
__device__ unsigned g_cmin[NCH], g_cmax[NCH];
__device__ unsigned g_hist[NCH][6], g_hist2[NCH][6];
__device__ float g_M[NCH][6], g_Z[NCH];
__device__ __align__(16) unsigned char g_gidx[GIDX_TOTAL];
__device__ __align__(16) float g_proc[306912];
__device__ unsigned g_pmin[5], g_pmax[5];
__device__ float g_resized[5 * 57600];
__device__ unsigned g_rmin[5], g_rmax[5];
__device__ float g_rsum[5];

__device__ __forceinline__ unsigned fenc(float f) {
    unsigned u = __float_as_uint(f);
    return (u & 0x80000000u) ? ~u : (u | 0x80000000u);
}
__device__ __forceinline__ float fdec(unsigned e) {
    return (e & 0x80000000u) ? __uint_as_float(e & 0x7fffffffu)
                             : __uint_as_float(~e);
}

__device__ __forceinline__ void gridbar(unsigned tgt) {
    __syncthreads();
    if (threadIdx.x == 0) {
        __threadfence();
        atomicAdd(&g_bar, 1u);
        volatile unsigned* p = &g_bar;
        while (*p < tgt) { __nanosleep(20); }
        __threadfence();
    }
    __syncthreads();
}

__global__ void k_init() {
    int i = blockIdx.x * 256 + threadIdx.x;
    if (i == 0) g_bar = 0u;
    if (i < 4) g_ctr[i] = 0u;
    if (i < NCH * 6) {
        ((unsigned*)g_hist)[i] = 0u;
        ((unsigned*)g_hist2)[i] = 0u;
    }
    if (i < NCH) { g_cmin[i] = 0xffffffffu; g_cmax[i] = 0u; }
    if (i < 76512) g_proc[230400 + i] = 0.f;   // l2..l5 (atomic-accumulated)
    if (i < 5) {
        g_pmin[i] = 0xffffffffu; g_pmax[i] = 0u;
        g_rmin[i] = 0xffffffffu; g_rmax[i] = 0u;
        g_rsum[i] = 0.f;
    }
}

// ---- masked float4 load (borders -> 0) ------------------------------------
template <int H, int W>
__device__ __forceinline__ void mask4(int fc, float4 v,
                                      float& v0, float& v1, float& v2, float& v3) {
    if constexpr (W % 4 == 0) {
        constexpr int W4 = W / 4;
        int row = fc / W4;
        int col = fc - row * W4;
        bool br = (row == 0) | (row == H - 1);
        v0 = (br | (col == 0))      ? 0.f : v.x;
        v1 = br                      ? 0.f : v.y;
        v2 = br                      ? 0.f : v.z;
        v3 = (br | (col == W4 - 1)) ? 0.f : v.w;
    } else {
        int e = fc * 4;
        int y0 = e / W, x0 = e - y0 * W;
        int y1 = (e+1) / W, x1 = (e+1) - y1 * W;
        int y2 = (e+2) / W, x2 = (e+2) - y2 * W;
        int y3 = (e+3) / W, x3 = (e+3) - y3 * W;
        v0 = ((y0==0)|(x0==0)|(y0==H-1)|(x0==W-1)) ? 0.f : v.x;
        v1 = ((y1==0)|(x1==0)|(y1==H-1)|(x1==W-1)) ? 0.f : v.y;
        v2 = ((y2==0)|(x2==0)|(y2==H-1)|(x2==W-1)) ? 0.f : v.z;
        v3 = ((y3==0)|(x3==0)|(y3==H-1)|(x3==W-1)) ? 0.f : v.w;
    }
}

// -------- P1 unit: min/max over one (channel, slice) -----------------------
template <int H, int W, int SL, int CHF4>
__device__ __forceinline__ void mm_unit(const float* __restrict__ in,
                                        int choff, int c, int s) {
    constexpr int F4PT = (SL + 255) / 256;
    const float4* p4 = (const float4*)in + (size_t)c * CHF4 + s * SL;
    const int fbase = s * SL;
    float mn = 0.f, mx = 0.f;   // 0 always present (borders)
#pragma unroll
    for (int j = 0; j < F4PT; j++) {
        int fl = j * 256 + threadIdx.x;
        if (SL % 256 == 0 || fl < SL) {
            float4 v = p4[fl];
            float v0, v1, v2, v3;
            mask4<H, W>(fbase + fl, v, v0, v1, v2, v3);
            mn = fminf(mn, fminf(fminf(v0, v1), fminf(v2, v3)));
            mx = fmaxf(mx, fmaxf(fmaxf(v0, v1), fmaxf(v2, v3)));
        }
    }
    unsigned emn = __reduce_min_sync(0xffffffffu, fenc(mn));
    unsigned emx = __reduce_max_sync(0xffffffffu, fenc(mx));
    if ((threadIdx.x & 31) == 0) {
        atomicMin(&g_cmin[choff + c], emn);
        atomicMax(&g_cmax[choff + c], emx);
    }
}

// -------- P2 unit: dual 6-bin hist + gidx map ------------------------------
// bin and gidx both derived from iu = floor(chp*6):
//   bin = min(5, iu>>8)   (== floor(rn(chp*3/128)) since /256 is exact pow2)
//   g   = min(5, max(0, iu-1))  (floor(x-1) == floor(x)-1)
template <int H, int W, int SL, int CHF4>
__device__ __forceinline__ void hist_unit(const float* __restrict__ in,
                                          int choff, size_t gidxoff,
                                          int c, int s, unsigned* sh) {
    constexpr int F4PT = (SL + 255) / 256;
    const int gc = choff + c;
    const float4* p4 = (const float4*)in + (size_t)c * CHF4 + s * SL;
    uchar4* go = (uchar4*)(g_gidx + gidxoff) + (size_t)c * CHF4 + s * SL;
    const int fbase = s * SL;
    const float mn = fdec(g_cmin[gc]);
    const float mx = fdec(g_cmax[gc]);
    const float rng = mx - mn;
    const bool zr = (rng == 0.f);
    unsigned long long pk1 = 0, pk2 = 0;   // 6 x 10-bit packed counters
#pragma unroll
    for (int j = 0; j < F4PT; j++) {
        int fl = j * 256 + threadIdx.x;
        if (SL % 256 == 0 || fl < SL) {
            float4 v = p4[fl];
            float vv[4];
            mask4<H, W>(fbase + fl, v, vv[0], vv[1], vv[2], vv[3]);
            unsigned gb[4];
#pragma unroll
            for (int k = 0; k < 4; k++) {
                float q = zr ? 0.f : __fdiv_rn(__fsub_rn(vv[k], mn), rng);
                float chp = __fmul_rn(q, 256.f);
                float u6 = __fmul_rn(chp, 6.f);
                int iu = (int)floorf(u6);
                int bin = min(5, iu >> 8);
                int g = min(5, max(0, iu - 1));
                pk1 += 1ull << (bin * 10);
                pk2 += 1ull << (g * 10);
                gb[k] = (unsigned)g;
            }
            go[fl] = make_uchar4(gb[0], gb[1], gb[2], gb[3]);
        }
    }
    if (threadIdx.x < 12) sh[threadIdx.x] = 0;
    __syncthreads();
#pragma unroll
    for (int b6 = 0; b6 < 6; b6++) {
        unsigned c1 = (unsigned)(pk1 >> (b6 * 10)) & 1023u;
        unsigned c2 = (unsigned)(pk2 >> (b6 * 10)) & 1023u;
        c1 = __reduce_add_sync(0xffffffffu, c1);
        c2 = __reduce_add_sync(0xffffffffu, c2);
        if ((threadIdx.x & 31) == 0) {
            if (c1) atomicAdd(&sh[b6], c1);
            if (c2) atomicAdd(&sh[6 + b6], c2);
        }
    }
    __syncthreads();
    if (threadIdx.x < 6 && sh[threadIdx.x])
        atomicAdd(&g_hist[gc][threadIdx.x], sh[threadIdx.x]);
    if (threadIdx.x >= 6 && threadIdx.x < 12 && sh[threadIdx.x])
        atomicAdd(&g_hist2[gc][threadIdx.x - 6], sh[threadIdx.x]);
    __syncthreads();
}

// -------- P3: closed-form per-channel tables -------------------------------
__device__ __forceinline__ void stats_ch(int gc) {
    int choff, H, W;
    if (gc < 64)       { choff = 0;   H = 480; W = 480; }
    else if (gc < 192) { choff = 64;  H = 240; W = 240; }
    else if (gc < 448) { choff = 192; H = 120; W = 120; }
    else if (gc < 960) { choff = 448; H = 60;  W = 60;  }
    else               { choff = 960; H = 30;  W = 30;  }
    const int c = gc - choff;
    const float Nf = (float)(H * W);
    const int Nb = 2 * (H + W) - 4;

    float mn = fdec(g_cmin[gc]), mx = fdec(g_cmax[gc]);
    float rng = mx - mn;

    float hl[6]; unsigned h2[6];
#pragma unroll
    for (int b = 0; b < 6; b++) {
        float pr = __fadd_rn(__fdiv_rn((float)g_hist[gc][b], Nf), 1e-4f);
        hl[b] = -logf(pr);
        h2[b] = g_hist2[gc][b];
    }
    float dmin = FLT_MAX, dmax = -FLT_MAX, s = 0.f;
#pragma unroll
    for (int b = 0; b < 6; b++) if (h2[b]) {
        dmin = fminf(dmin, hl[b]); dmax = fmaxf(dmax, hl[b]);
        s += (float)h2[b] * hl[b];
    }
    float drng = dmax - dmin;
    float L[6];
    if (drng == 0.f) {
#pragma unroll
        for (int b = 0; b < 6; b++) L[b] = 0.f;
    } else {
        float meann = (s / Nf - dmin) / drng;
        float t = 1.f - meann;
        float w1 = t * t;
#pragma unroll
        for (int b = 0; b < 6; b++) L[b] = (hl[b] - dmin) / drng * w1;
    }
    int gb = 0;
    if (rng != 0.f) {
        float chpb = __fmul_rn(__fdiv_rn(__fsub_rn(0.f, mn), rng), 256.f);
        int g = (int)truncf(__fsub_rn(__fmul_rn(chpb, 6.f), 1.f));
        gb = min(5, max(0, g));
    }
    float mmin = FLT_MAX, mmax = -FLT_MAX, s2 = 0.f;
#pragma unroll
    for (int b = 0; b < 6; b++) {
        unsigned cnt = h2[b];
        if (c > 0 && b == gb) cnt -= (unsigned)Nb;
        if (cnt) {
            mmin = fminf(mmin, L[b]); mmax = fmaxf(mmax, L[b]);
            s2 += (float)cnt * L[b];
        }
    }
    if (c > 0) { mmin = fminf(mmin, 0.f); mmax = fmaxf(mmax, 0.f); }
    float mrng = mmax - mmin;
    if (mrng == 0.f) {
#pragma unroll
        for (int b = 0; b < 6; b++) g_M[gc][b] = 0.f;
        g_Z[gc] = 0.f;
    } else {
        float mmean = s2 / Nf;
        float t = mmax - mmean;
        float w2 = t * t;
#pragma unroll
        for (int b = 0; b < 6; b++) g_M[gc][b] = (L[b] - mmin) / mrng * w2;
        g_Z[gc] = (0.f - mmin) / mrng * w2;
    }
}

// -------- P4 unit: proc += sum of 64 channels of M[c][gidx] ----------------
template <int C, int H, int W, bool DIRECT>
__device__ __forceinline__ void proc_unit(size_t gidxoff, int procoff,
                                          int choff, int pxblk, int cslice,
                                          float* sM, float* sZ) {
    constexpr int CS = 64;
    constexpr int HW = H * W;
    constexpr int NQ = HW / 4;
    const int cbeg = cslice * CS;
    for (int i = threadIdx.x; i < CS * 6; i += 256)
        sM[i] = ((const float*)g_M)[(choff + cbeg) * 6 + i];
    if (threadIdx.x < CS) sZ[threadIdx.x] = g_Z[choff + cbeg + threadIdx.x];
    __syncthreads();

    int q = pxblk * 256 + threadIdx.x;
    bool act = q < NQ;
    bool bf0 = false, bf1 = false, bf2 = false, bf3 = false;
    if (act) {
        if constexpr (W % 4 == 0) {
            constexpr int W4 = W / 4;
            int row = q / W4, col = q - row * W4;
            bool br = (row == 0) | (row == H - 1);
            bf0 = br | (col == 0); bf1 = br; bf2 = br;
            bf3 = br | (col == W4 - 1);
        } else {
            int e = q * 4;
#pragma unroll
            for (int k = 0; k < 4; k++) {
                int y = (e + k) / W, x = (e + k) - y * W;
                bool bb = (y == 0) | (x == 0) | (y == H - 1) | (x == W - 1);
                if (k == 0) bf0 = bb; else if (k == 1) bf1 = bb;
                else if (k == 2) bf2 = bb; else bf3 = bb;
            }
        }
    }
    bool anyb = __any_sync(0xffffffffu, act && (bf0 | bf1 | bf2 | bf3));
    float a0 = 0.f, a1 = 0.f, a2 = 0.f, a3 = 0.f;
    if (act) {
        const uchar4* gp = (const uchar4*)(g_gidx + gidxoff) + q;
        if (!anyb) {
#pragma unroll 8
            for (int cc = 0; cc < CS; cc++) {
                uchar4 gv = gp[(size_t)(cbeg + cc) * NQ];
                const float* mc = sM + cc * 6;
                a0 += mc[gv.x]; a1 += mc[gv.y]; a2 += mc[gv.z]; a3 += mc[gv.w];
            }
        } else {
#pragma unroll 8
            for (int cc = 0; cc < CS; cc++) {
                uchar4 gv = gp[(size_t)(cbeg + cc) * NQ];
                const float* mc = sM + cc * 6;
                bool ch0 = (cbeg + cc) == 0;   // layer ch 0 keeps border
                float z = sZ[cc];
                a0 += (bf0 && !ch0) ? z : mc[gv.x];
                a1 += (bf1 && !ch0) ? z : mc[gv.y];
                a2 += (bf2 && !ch0) ? z : mc[gv.z];
                a3 += (bf3 && !ch0) ? z : mc[gv.w];
            }
        }
        if constexpr (DIRECT) {
            ((float4*)(g_proc + procoff))[q] = make_float4(a0, a1, a2, a3);
        } else {
            float* pp = g_proc + procoff + q * 4;
            atomicAdd(pp + 0, a0); atomicAdd(pp + 1, a1);
            atomicAdd(pp + 2, a2); atomicAdd(pp + 3, a3);
        }
    }
}

// -------- P6 unit: resize + fused normalize/threshold + r-stats ------------
template <int S>
__device__ __forceinline__ void resize_unit(int b, int procoff, int layer,
                                            unsigned* sred, float* ssum) {
    int idx = b * 256 + threadIdx.x;   // 57600 = 225*256 exact
    int oy = idx / 240, ox = idx - oy * 240;
    float pmn = fdec(g_pmin[layer]);
    float pmx = fdec(g_pmax[layer]);
    float prng = pmx - pmn;
    constexpr float inv = (float)S / 240.f;
    constexpr float ks = (S > 240) ? inv : 1.f;
    constexpr float iks = 1.f / ks;
    float fy = (oy + 0.5f) * inv - 0.5f;
    float fx = (ox + 0.5f) * inv - 0.5f;
    int y0 = max(0, (int)ceilf(fy - ks)), y1 = min(S - 1, (int)floorf(fy + ks));
    int x0 = max(0, (int)ceilf(fx - ks)), x1 = min(S - 1, (int)floorf(fx + ks));
    float wy[4], wx[4];
    float sy = 0.f, sx = 0.f;
#pragma unroll
    for (int j = 0; j < 4; j++) {
        int yy = y0 + j;
        float w = (yy <= y1) ? fmaxf(0.f, 1.f - fabsf(fy - (float)yy) * iks) : 0.f;
        wy[j] = w; sy += w;
        int xx = x0 + j;
        float v = (xx <= x1) ? fmaxf(0.f, 1.f - fabsf(fx - (float)xx) * iks) : 0.f;
        wx[j] = v; sx += v;
    }
#pragma unroll
    for (int j = 0; j < 4; j++) {
        wy[j] = __fdiv_rn(wy[j], sy);
        wx[j] = __fdiv_rn(wx[j], sx);
    }
    const float* p = g_proc + procoff;
    float acc = 0.f;
#pragma unroll
    for (int jy = 0; jy < 4; jy++) {
        if (y0 + jy > y1) break;
        const float* row = p + (y0 + jy) * S;
        float r = 0.f;
#pragma unroll
        for (int jx = 0; jx < 4; jx++) {
            if (x0 + jx > x1) break;
            float v = row[x0 + jx];
            float n = (prng == 0.f) ? 0.f : __fdiv_rn(__fsub_rn(v, pmn), prng);
            n = (n < 0.2f) ? 0.f : n;
            r += wx[jx] * n;
        }
        acc += wy[jy] * r;
    }
    g_resized[layer * 57600 + idx] = acc;

    unsigned* smn = sred; unsigned* smx = sred + 8;
    unsigned emn = __reduce_min_sync(0xffffffffu, fenc(acc));
    unsigned emx = __reduce_max_sync(0xffffffffu, fenc(acc));
    float wsum = acc;
#pragma unroll
    for (int o = 16; o; o >>= 1) wsum += __shfl_xor_sync(0xffffffffu, wsum, o);
    if ((threadIdx.x & 31) == 0) {
        int w = threadIdx.x >> 5;
        smn[w] = emn; smx[w] = emx; ssum[w] = wsum;
    }
    __syncthreads();
    if (threadIdx.x == 0) {
        unsigned a = smn[0], bb = smx[0]; float s = ssum[0];
#pragma unroll
        for (int w = 1; w < 8; w++) {
            a = min(a, smn[w]); bb = max(bb, smx[w]); s += ssum[w];
        }
        atomicMin(&g_rmin[layer], a);
        atomicMax(&g_rmax[layer], bb);
        atomicAdd(&g_rsum[layer], s);
    }
    __syncthreads();
}

// ---------------------------- the fused kernel -----------------------------
__global__ __launch_bounds__(256, 5) void k_main(
    const float* __restrict__ l1, const float* __restrict__ l2,
    const float* __restrict__ l3, const float* __restrict__ l4,
    const float* __restrict__ l5, float* __restrict__ out) {
    __shared__ float sM[64 * 6];
    __shared__ float sZ[64];
    __shared__ unsigned sred[24];
    __shared__ float ssum[8];
    __shared__ int s_u;

    // ---- P1: minmax, work-stolen (4608 units) ----
    for (;;) {
        __syncthreads();
        if (threadIdx.x == 0) s_u = (int)atomicAdd(&g_ctr[0], 1u);
        __syncthreads();
        int u = s_u;
        if (u >= 4608) break;
        if (u < 2048)      mm_unit<480, 480, 1800, 57600>(l1, 0, u >> 5, u & 31);
        else if (u < 3072) mm_unit<240, 240, 1800, 14400>(l2, 64, (u - 2048) >> 3, (u - 2048) & 7);
        else if (u < 3584) mm_unit<120, 120, 1800, 3600>(l3, 192, (u - 3072) >> 1, (u - 3072) & 1);
        else if (u < 4096) mm_unit<60, 60, 900, 900>(l4, 448, u - 3584, 0);
        else               mm_unit<30, 30, 225, 225>(l5, 960, u - 4096, 0);
    }
    gridbar(1 * NB);

    // ---- P2: hist + gidx, work-stolen (input L2-resident) ----
    for (;;) {
        __syncthreads();
        if (threadIdx.x == 0) s_u = (int)atomicAdd(&g_ctr[1], 1u);
        __syncthreads();
        int u = s_u;
        if (u >= 4608) break;
        if (u < 2048)      hist_unit<480, 480, 1800, 57600>(l1, 0, 0u, u >> 5, u & 31, sred);
        else if (u < 3072) hist_unit<240, 240, 1800, 14400>(l2, 64, 14745600u, (u - 2048) >> 3, (u - 2048) & 7, sred);
        else if (u < 3584) hist_unit<120, 120, 1800, 3600>(l3, 192, 22118400u, (u - 3072) >> 1, (u - 3072) & 1, sred);
        else if (u < 4096) hist_unit<60, 60, 900, 900>(l4, 448, 25804800u, u - 3584, 0, sred);
        else               hist_unit<30, 30, 225, 225>(l5, 960, 27648000u, u - 4096, 0, sred);
    }
    gridbar(2 * NB);

    // ---- P3: per-channel tables (46 blocks x 32 threads) ----
    if (blockIdx.x < 46 && threadIdx.x < 32) {
        int gc = blockIdx.x * 32 + threadIdx.x;
        if (gc < NCH) stats_ch(gc);
    }
    gridbar(3 * NB);

    // ---- P4: proc sums, work-stolen (439 uniform units) ----
    for (;;) {
        __syncthreads();
        if (threadIdx.x == 0) s_u = (int)atomicAdd(&g_ctr[2], 1u);
        __syncthreads();
        int u = s_u;
        if (u >= 439) break;
        if (u < 225)       proc_unit<64, 480, 480, true>(0u, 0, 0, u, 0, sM, sZ);
        else if (u < 339) { int i = u - 225;
                            proc_unit<128, 240, 240, false>(14745600u, 230400, 64, i >> 1, i & 1, sM, sZ); }
        else if (u < 399) { int i = u - 339;
                            proc_unit<256, 120, 120, false>(22118400u, 288000, 192, i >> 2, i & 3, sM, sZ); }
        else if (u < 431) { int i = u - 399;
                            proc_unit<512, 60, 60, false>(25804800u, 302400, 448, i >> 3, i & 7, sM, sZ); }
        else              { int i = u - 431;
                            proc_unit<512, 30, 30, false>(27648000u, 306000, 960, 0, i, sM, sZ); }
    }
    gridbar(4 * NB);

    // ---- P5: all-layer pmin/pmax (76725 float4, 1/thread) ----
    {
        if (threadIdx.x < 5) { sred[threadIdx.x] = 0xffffffffu; sred[12 + threadIdx.x] = 0u; }
        __syncthreads();
        int tg = blockIdx.x * 256 + threadIdx.x;
        if (tg < 76725) {
            float4 v = ((const float4*)g_proc)[tg];
            int l = (tg < 57600) ? 0 : (tg < 72000) ? 1 : (tg < 75600) ? 2
                  : (tg < 76500) ? 3 : 4;
            float mn = fminf(fminf(v.x, v.y), fminf(v.z, v.w));
            float mx = fmaxf(fmaxf(v.x, v.y), fmaxf(v.z, v.w));
            atomicMin(&sred[l], fenc(mn));
            atomicMax(&sred[12 + l], fenc(mx));
        }
        __syncthreads();
        if (threadIdx.x < 5) {
            atomicMin(&g_pmin[threadIdx.x], sred[threadIdx.x]);
            atomicMax(&g_pmax[threadIdx.x], sred[12 + threadIdx.x]);
        }
    }
    gridbar(5 * NB);

    // ---- P6: resize, work-stolen (1125 units) ----
    for (;;) {
        __syncthreads();
        if (threadIdx.x == 0) s_u = (int)atomicAdd(&g_ctr[3], 1u);
        __syncthreads();
        int u = s_u;
        if (u >= 1125) break;
        if (u < 225)      resize_unit<480>(u, 0, 0, sred, ssum);
        else if (u < 450) resize_unit<240>(u - 225, 230400, 1, sred, ssum);
        else if (u < 675) resize_unit<120>(u - 450, 288000, 2, sred, ssum);
        else if (u < 900) resize_unit<60>(u - 675, 302400, 3, sred, ssum);
        else              resize_unit<30>(u - 900, 306000, 4, sred, ssum);
    }
    gridbar(6 * NB);

    // ---- P7: final groups + sum ----
    if (blockIdx.x < 225) {
        int idx = blockIdx.x * 256 + threadIdx.x;
        float s = 0.f;
#pragma unroll
        for (int l = 0; l < 5; l++) {
            float v = g_resized[l * 57600 + idx];
            float rmn = fdec(g_rmin[l]);
            float rmx = fdec(g_rmax[l]);
            float rrng = rmx - rmn;
            float rmean = g_rsum[l] / 57600.f;
            float t = rmx - rmean;
            float w3 = t * t;
            float g = (rrng == 0.f || w3 == 0.f)
                      ? 0.f
                      : __fmul_rn(__fdiv_rn(__fsub_rn(v, rmn), rrng), 256.f);
            s += g;
            out[57600 + idx * 5 + l] = g;
        }
        out[idx] = s;
    }
}

extern "C" void kernel_launch(void* const* d_in, const int* in_sizes, int n_in,
                              void* d_out, int out_size) {
    const float* l1 = (const float*)d_in[0];
    const float* l2 = (const float*)d_in[1];
    const float* l3 = (const float*)d_in[2];
    const float* l4 = (const float*)d_in[3];
    const float* l5 = (const float*)d_in[4];
    float* out = (float*)d_out;

    k_init<<<300, 256>>>();
    k_main<<<NB, 256>>>(l1, l2, l3, l4, l5, out);
}

// round 7
// speedup vs baseline: 1.0097x; 1.0097x over previous
#include <cuda_runtime.h>
#include <cuda_bf16.h>
#include <math.h>
#include <float.h>
#include <stdint.h>

// ---------------------------------------------------------------------------
// DeepRare, persistent kernel, instruction-lean P2:
//  P1 minmax -> P2 hist+gidx (FFMA binning, 32-bit packed counters) ->
//  P3 stats -> P4 proc -> P5 pminmax -> P6 resize -> P7 final
// ---------------------------------------------------------------------------

#define NCH 1472
#define GIDX_TOTAL 28108800
#define NB 740          // 148 SMs x 5 blocks (fits 152-SM GB300 too)

__device__ unsigned g_bar;
__device__ unsigned g_ctr[4];
__device__ unsigned g_cmin[NCH], g_cmax[NCH];
__device__ unsigned g_hist[NCH][6], g_hist2[NCH][6];
__device__ float g_M[NCH][6], g_Z[NCH];
__device__ __align__(16) unsigned char g_gidx[GIDX_TOTAL];
__device__ __align__(16) float g_proc[306912];
__device__ unsigned g_pmin[5], g_pmax[5];
__device__ float g_resized[5 * 57600];
__device__ unsigned g_rmin[5], g_rmax[5];
__device__ float g_rsum[5];

__device__ __forceinline__ unsigned fenc(float f) {
    unsigned u = __float_as_uint(f);
    return (u & 0x80000000u) ? ~u : (u | 0x80000000u);
}
__device__ __forceinline__ float fdec(unsigned e) {
    return (e & 0x80000000u) ? __uint_as_float(e & 0x7fffffffu)
                             : __uint_as_float(~e);
}

__device__ __forceinline__ void gridbar(unsigned tgt) {
    __syncthreads();
    if (threadIdx.x == 0) {
        __threadfence();
        atomicAdd(&g_bar, 1u);
        volatile unsigned* p = &g_bar;
        while (*p < tgt) { __nanosleep(20); }
        __threadfence();
    }
    __syncthreads();
}

__global__ void k_init() {
    int i = blockIdx.x * 256 + threadIdx.x;
    if (i == 0) g_bar = 0u;
    if (i < 4) g_ctr[i] = 0u;
    if (i < NCH * 6) {
        ((unsigned*)g_hist)[i] = 0u;
        ((unsigned*)g_hist2)[i] = 0u;
    }
    if (i < NCH) { g_cmin[i] = 0xffffffffu; g_cmax[i] = 0u; }
    if (i < 76512) g_proc[230400 + i] = 0.f;   // l2..l5 (atomic-accumulated)
    if (i < 5) {
        g_pmin[i] = 0xffffffffu; g_pmax[i] = 0u;
        g_rmin[i] = 0xffffffffu; g_rmax[i] = 0u;
        g_rsum[i] = 0.f;
    }
}

// ---- masked float4 load (borders -> 0) ------------------------------------
template <int H, int W>
__device__ __forceinline__ void mask4(int fc, float4 v,
                                      float& v0, float& v1, float& v2, float& v3) {
    if constexpr (W % 4 == 0) {
        constexpr int W4 = W / 4;
        int row = fc / W4;
        int col = fc - row * W4;
        bool br = (row == 0) | (row == H - 1);
        v0 = (br | (col == 0))      ? 0.f : v.x;
        v1 = br                      ? 0.f : v.y;
        v2 = br                      ? 0.f : v.z;
        v3 = (br | (col == W4 - 1)) ? 0.f : v.w;
    } else {
        int e = fc * 4;
        int y0 = e / W, x0 = e - y0 * W;
        int y1 = (e+1) / W, x1 = (e+1) - y1 * W;
        int y2 = (e+2) / W, x2 = (e+2) - y2 * W;
        int y3 = (e+3) / W, x3 = (e+3) - y3 * W;
        v0 = ((y0==0)|(x0==0)|(y0==H-1)|(x0==W-1)) ? 0.f : v.x;
        v1 = ((y1==0)|(x1==0)|(y1==H-1)|(x1==W-1)) ? 0.f : v.y;
        v2 = ((y2==0)|(x2==0)|(y2==H-1)|(x2==W-1)) ? 0.f : v.z;
        v3 = ((y3==0)|(x3==0)|(y3==H-1)|(x3==W-1)) ? 0.f : v.w;
    }
}

// -------- P1 unit: min/max over one (channel, slice), branch-free ----------
// Clamped index: inactive threads re-read fl=0 of the same slice; duplicate
// elements cannot change a min/max.
template <int H, int W, int SL, int CHF4>
__device__ __forceinline__ void mm_unit(const float* __restrict__ in,
                                        int choff, int c, int s) {
    constexpr int F4PT = (SL + 255) / 256;
    const float4* p4 = (const float4*)in + (size_t)c * CHF4 + (size_t)s * SL;
    const int fbase = s * SL;
    float mn = 0.f, mx = 0.f;   // 0 always present in channel (borders)
#pragma unroll
    for (int j = 0; j < F4PT; j++) {
        int fl = j * 256 + threadIdx.x;
        int fli = (SL % 256 == 0) ? fl : min(fl, SL - 1);
        float4 v = p4[fli];
        float v0, v1, v2, v3;
        mask4<H, W>(fbase + fli, v, v0, v1, v2, v3);
        mn = fminf(mn, fminf(fminf(v0, v1), fminf(v2, v3)));
        mx = fmaxf(mx, fmaxf(fmaxf(v0, v1), fmaxf(v2, v3)));
    }
    unsigned emn = __reduce_min_sync(0xffffffffu, fenc(mn));
    unsigned emx = __reduce_max_sync(0xffffffffu, fenc(mx));
    if ((threadIdx.x & 31) == 0) {
        atomicMin(&g_cmin[choff + c], emn);
        atomicMax(&g_cmax[choff + c], emx);
    }
}

// -------- P2 unit: dual 6-bin hist + gidx map (FFMA binning) ---------------
// u6 = (v - mn) * 1536/rng  (~= chp*6); iu = floor(u6)
//   bin = clamp(iu>>8, 0, 5); g = clamp(iu-1, 0, 5)
// Counters: 32-bit, bins 0..4 in 5x6-bit fields; bin-5 adds hit scratch bits
// 30..31 (overflow drops out of the register); bin5 = nact - sum(f0..f4).
template <int H, int W, int SL, int CHF4>
__device__ __forceinline__ void hist_unit(const float* __restrict__ in,
                                          int choff, size_t gidxoff,
                                          int c, int s) {
    constexpr int F4PT = (SL + 255) / 256;
    const int gc = choff + c;
    const float4* p4 = (const float4*)in + (size_t)c * CHF4 + (size_t)s * SL;
    uchar4* go = (uchar4*)(g_gidx + gidxoff) + (size_t)c * CHF4 + (size_t)s * SL;
    const int fbase = s * SL;
    const float mn = fdec(g_cmin[gc]);
    const float mx = fdec(g_cmax[gc]);
    const float rng = mx - mn;
    float inv6, mn6;
    if (rng == 0.f) { inv6 = 0.f; mn6 = 0.f; }
    else { inv6 = __fdiv_rn(1536.f, rng); mn6 = __fmul_rn(-mn, inv6); }
    unsigned pk1 = 0u, pk2 = 0u, nact = 0u;
#pragma unroll
    for (int j = 0; j < F4PT; j++) {
        int fl = j * 256 + threadIdx.x;
        bool act = (SL % 256 == 0) || (fl < SL);
        int fli = act ? fl : 0;
        float4 v = p4[fli];
        float vv[4];
        mask4<H, W>(fbase + fli, v, vv[0], vv[1], vv[2], vv[3]);
        unsigned gb[4]; unsigned a1 = 0u, a2 = 0u;
#pragma unroll
        for (int k = 0; k < 4; k++) {
            float u6 = __fmaf_rn(vv[k], inv6, mn6);
            int iu = (int)floorf(u6);
            int bin = min(5, max(0, iu >> 8));
            int g = min(5, max(0, iu - 1));
            a1 += 1u << (bin * 6);
            a2 += 1u << (g * 6);
            gb[k] = (unsigned)g;
        }
        if (act) {
            pk1 += a1; pk2 += a2; nact += 4u;
            go[fl] = make_uchar4(gb[0], gb[1], gb[2], gb[3]);
        }
    }
    unsigned f1[6], f2[6], s1 = 0u, s2 = 0u;
#pragma unroll
    for (int b = 0; b < 5; b++) {
        f1[b] = (pk1 >> (b * 6)) & 63u; s1 += f1[b];
        f2[b] = (pk2 >> (b * 6)) & 63u; s2 += f2[b];
    }
    f1[5] = nact - s1; f2[5] = nact - s2;
#pragma unroll
    for (int b = 0; b < 6; b++) {
        f1[b] = __reduce_add_sync(0xffffffffu, f1[b]);
        f2[b] = __reduce_add_sync(0xffffffffu, f2[b]);
    }
    if ((threadIdx.x & 31) == 0) {
#pragma unroll
        for (int b = 0; b < 6; b++) {
            if (f1[b]) atomicAdd(&g_hist[gc][b], f1[b]);
            if (f2[b]) atomicAdd(&g_hist2[gc][b], f2[b]);
        }
    }
}

// -------- P3: closed-form per-channel tables -------------------------------
__device__ __forceinline__ void stats_ch(int gc) {
    int choff, H, W;
    if (gc < 64)       { choff = 0;   H = 480; W = 480; }
    else if (gc < 192) { choff = 64;  H = 240; W = 240; }
    else if (gc < 448) { choff = 192; H = 120; W = 120; }
    else if (gc < 960) { choff = 448; H = 60;  W = 60;  }
    else               { choff = 960; H = 30;  W = 30;  }
    const int c = gc - choff;
    const float Nf = (float)(H * W);
    const int Nb = 2 * (H + W) - 4;

    float mn = fdec(g_cmin[gc]), mx = fdec(g_cmax[gc]);
    float rng = mx - mn;

    float hl[6]; unsigned h2[6];
#pragma unroll
    for (int b = 0; b < 6; b++) {
        float pr = __fadd_rn(__fdiv_rn((float)g_hist[gc][b], Nf), 1e-4f);
        hl[b] = -logf(pr);
        h2[b] = g_hist2[gc][b];
    }
    float dmin = FLT_MAX, dmax = -FLT_MAX, s = 0.f;
#pragma unroll
    for (int b = 0; b < 6; b++) if (h2[b]) {
        dmin = fminf(dmin, hl[b]); dmax = fmaxf(dmax, hl[b]);
        s += (float)h2[b] * hl[b];
    }
    float drng = dmax - dmin;
    float L[6];
    if (drng == 0.f) {
#pragma unroll
        for (int b = 0; b < 6; b++) L[b] = 0.f;
    } else {
        float meann = (s / Nf - dmin) / drng;
        float t = 1.f - meann;
        float w1 = t * t;
#pragma unroll
        for (int b = 0; b < 6; b++) L[b] = (hl[b] - dmin) / drng * w1;
    }
    // border gidx: EXACTLY the P2 formula applied to v=0 (vv=0 -> u6 = mn6)
    int gb = 0;
    if (rng != 0.f) {
        float inv6 = __fdiv_rn(1536.f, rng);
        float mn6 = __fmul_rn(-mn, inv6);
        int iu = (int)floorf(mn6);
        gb = min(5, max(0, iu - 1));
    }
    float mmin = FLT_MAX, mmax = -FLT_MAX, s2 = 0.f;
#pragma unroll
    for (int b = 0; b < 6; b++) {
        unsigned cnt = h2[b];
        if (c > 0 && b == gb) cnt -= (unsigned)Nb;
        if (cnt) {
            mmin = fminf(mmin, L[b]); mmax = fmaxf(mmax, L[b]);
            s2 += (float)cnt * L[b];
        }
    }
    if (c > 0) { mmin = fminf(mmin, 0.f); mmax = fmaxf(mmax, 0.f); }
    float mrng = mmax - mmin;
    if (mrng == 0.f) {
#pragma unroll
        for (int b = 0; b < 6; b++) g_M[gc][b] = 0.f;
        g_Z[gc] = 0.f;
    } else {
        float mmean = s2 / Nf;
        float t = mmax - mmean;
        float w2 = t * t;
#pragma unroll
        for (int b = 0; b < 6; b++) g_M[gc][b] = (L[b] - mmin) / mrng * w2;
        g_Z[gc] = (0.f - mmin) / mrng * w2;
    }
}

// -------- P4 unit: proc += sum of 64 channels of M[c][gidx] ----------------
template <int C, int H, int W, bool DIRECT>
__device__ __forceinline__ void proc_unit(size_t gidxoff, int procoff,
                                          int choff, int pxblk, int cslice,
                                          float* sM, float* sZ) {
    constexpr int CS = 64;
    constexpr int HW = H * W;
    constexpr int NQ = HW / 4;
    const int cbeg = cslice * CS;
    for (int i = threadIdx.x; i < CS * 6; i += 256)
        sM[i] = ((const float*)g_M)[(choff + cbeg) * 6 + i];
    if (threadIdx.x < CS) sZ[threadIdx.x] = g_Z[choff + cbeg + threadIdx.x];
    __syncthreads();

    int q = pxblk * 256 + threadIdx.x;
    bool act = q < NQ;
    bool bf0 = false, bf1 = false, bf2 = false, bf3 = false;
    if (act) {
        if constexpr (W % 4 == 0) {
            constexpr int W4 = W / 4;
            int row = q / W4, col = q - row * W4;
            bool br = (row == 0) | (row == H - 1);
            bf0 = br | (col == 0); bf1 = br; bf2 = br;
            bf3 = br | (col == W4 - 1);
        } else {
            int e = q * 4;
#pragma unroll
            for (int k = 0; k < 4; k++) {
                int y = (e + k) / W, x = (e + k) - y * W;
                bool bb = (y == 0) | (x == 0) | (y == H - 1) | (x == W - 1);
                if (k == 0) bf0 = bb; else if (k == 1) bf1 = bb;
                else if (k == 2) bf2 = bb; else bf3 = bb;
            }
        }
    }
    bool anyb = __any_sync(0xffffffffu, act && (bf0 | bf1 | bf2 | bf3));
    float a0 = 0.f, a1 = 0.f, a2 = 0.f, a3 = 0.f;
    if (act) {
        const uchar4* gp = (const uchar4*)(g_gidx + gidxoff) + q;
        if (!anyb) {
#pragma unroll 8
            for (int cc = 0; cc < CS; cc++) {
                uchar4 gv = gp[(size_t)(cbeg + cc) * NQ];
                const float* mc = sM + cc * 6;
                a0 += mc[gv.x]; a1 += mc[gv.y]; a2 += mc[gv.z]; a3 += mc[gv.w];
            }
        } else {
#pragma unroll 8
            for (int cc = 0; cc < CS; cc++) {
                uchar4 gv = gp[(size_t)(cbeg + cc) * NQ];
                const float* mc = sM + cc * 6;
                bool ch0 = (cbeg + cc) == 0;   // layer ch 0 keeps border
                float z = sZ[cc];
                a0 += (bf0 && !ch0) ? z : mc[gv.x];
                a1 += (bf1 && !ch0) ? z : mc[gv.y];
                a2 += (bf2 && !ch0) ? z : mc[gv.z];
                a3 += (bf3 && !ch0) ? z : mc[gv.w];
            }
        }
        if constexpr (DIRECT) {
            ((float4*)(g_proc + procoff))[q] = make_float4(a0, a1, a2, a3);
        } else {
            float* pp = g_proc + procoff + q * 4;
            atomicAdd(pp + 0, a0); atomicAdd(pp + 1, a1);
            atomicAdd(pp + 2, a2); atomicAdd(pp + 3, a3);
        }
    }
}

// -------- P6 unit: resize + fused normalize/threshold + r-stats ------------
template <int S>
__device__ __forceinline__ void resize_unit(int b, int procoff, int layer,
                                            unsigned* sred, float* ssum) {
    int idx = b * 256 + threadIdx.x;   // 57600 = 225*256 exact
    int oy = idx / 240, ox = idx - oy * 240;
    float pmn = fdec(g_pmin[layer]);
    float pmx = fdec(g_pmax[layer]);
    float prng = pmx - pmn;
    constexpr float inv = (float)S / 240.f;
    constexpr float ks = (S > 240) ? inv : 1.f;
    constexpr float iks = 1.f / ks;
    float fy = (oy + 0.5f) * inv - 0.5f;
    float fx = (ox + 0.5f) * inv - 0.5f;
    int y0 = max(0, (int)ceilf(fy - ks)), y1 = min(S - 1, (int)floorf(fy + ks));
    int x0 = max(0, (int)ceilf(fx - ks)), x1 = min(S - 1, (int)floorf(fx + ks));
    float wy[4], wx[4];
    float sy = 0.f, sx = 0.f;
#pragma unroll
    for (int j = 0; j < 4; j++) {
        int yy = y0 + j;
        float w = (yy <= y1) ? fmaxf(0.f, 1.f - fabsf(fy - (float)yy) * iks) : 0.f;
        wy[j] = w; sy += w;
        int xx = x0 + j;
        float v = (xx <= x1) ? fmaxf(0.f, 1.f - fabsf(fx - (float)xx) * iks) : 0.f;
        wx[j] = v; sx += v;
    }
#pragma unroll
    for (int j = 0; j < 4; j++) {
        wy[j] = __fdiv_rn(wy[j], sy);
        wx[j] = __fdiv_rn(wx[j], sx);
    }
    const float* p = g_proc + procoff;
    float acc = 0.f;
#pragma unroll
    for (int jy = 0; jy < 4; jy++) {
        if (y0 + jy > y1) break;
        const float* row = p + (y0 + jy) * S;
        float r = 0.f;
#pragma unroll
        for (int jx = 0; jx < 4; jx++) {
            if (x0 + jx > x1) break;
            float v = row[x0 + jx];
            float n = (prng == 0.f) ? 0.f : __fdiv_rn(__fsub_rn(v, pmn), prng);
            n = (n < 0.2f) ? 0.f : n;
            r += wx[jx] * n;
        }
        acc += wy[jy] * r;
    }
    g_resized[layer * 57600 + idx] = acc;

    unsigned* smn = sred; unsigned* smx = sred + 8;
    unsigned emn = __reduce_min_sync(0xffffffffu, fenc(acc));
    unsigned emx = __reduce_max_sync(0xffffffffu, fenc(acc));
    float wsum = acc;
#pragma unroll
    for (int o = 16; o; o >>= 1) wsum += __shfl_xor_sync(0xffffffffu, wsum, o);
    if ((threadIdx.x & 31) == 0) {
        int w = threadIdx.x >> 5;
        smn[w] = emn; smx[w] = emx; ssum[w] = wsum;
    }
    __syncthreads();
    if (threadIdx.x == 0) {
        unsigned a = smn[0], bb = smx[0]; float s = ssum[0];
#pragma unroll
        for (int w = 1; w < 8; w++) {
            a = min(a, smn[w]); bb = max(bb, smx[w]); s += ssum[w];
        }
        atomicMin(&g_rmin[layer], a);
        atomicMax(&g_rmax[layer], bb);
        atomicAdd(&g_rsum[layer], s);
    }
    __syncthreads();
}

// ---------------------------- the fused kernel -----------------------------
__global__ __launch_bounds__(256, 5) void k_main(
    const float* __restrict__ l1, const float* __restrict__ l2,
    const float* __restrict__ l3, const float* __restrict__ l4,
    const float* __restrict__ l5, float* __restrict__ out) {
    __shared__ float sM[64 * 6];
    __shared__ float sZ[64];
    __shared__ unsigned sred[24];
    __shared__ float ssum[8];
    __shared__ int s_u;

    // ---- P1: minmax, latency-hidden work-stealing (4608 units) ----
    if (threadIdx.x == 0) s_u = (int)atomicAdd(&g_ctr[0], 1u);
    __syncthreads();
    {
        int u = s_u;
        while (u < 4608) {
            __syncthreads();
            if (threadIdx.x == 0) s_u = (int)atomicAdd(&g_ctr[0], 1u);
            if (u < 2048)      mm_unit<480, 480, 1800, 57600>(l1, 0, u >> 5, u & 31);
            else if (u < 3072) mm_unit<240, 240, 1800, 14400>(l2, 64, (u - 2048) >> 3, (u - 2048) & 7);
            else if (u < 3584) mm_unit<120, 120, 1800, 3600>(l3, 192, (u - 3072) >> 1, (u - 3072) & 1);
            else if (u < 4096) mm_unit<60, 60, 900, 900>(l4, 448, u - 3584, 0);
            else               mm_unit<30, 30, 225, 225>(l5, 960, u - 4096, 0);
            __syncthreads();
            u = s_u;
        }
    }
    gridbar(1 * NB);

    // ---- P2: hist + gidx, reversed order (recent layers L2-hot) ----
    if (threadIdx.x == 0) s_u = (int)atomicAdd(&g_ctr[1], 1u);
    __syncthreads();
    {
        int ur = s_u;
        while (ur < 4608) {
            __syncthreads();
            if (threadIdx.x == 0) s_u = (int)atomicAdd(&g_ctr[1], 1u);
            int u = 4607 - ur;
            if (u < 2048)      hist_unit<480, 480, 1800, 57600>(l1, 0, 0u, u >> 5, u & 31);
            else if (u < 3072) hist_unit<240, 240, 1800, 14400>(l2, 64, 14745600u, (u - 2048) >> 3, (u - 2048) & 7);
            else if (u < 3584) hist_unit<120, 120, 1800, 3600>(l3, 192, 22118400u, (u - 3072) >> 1, (u - 3072) & 1);
            else if (u < 4096) hist_unit<60, 60, 900, 900>(l4, 448, 25804800u, u - 3584, 0);
            else               hist_unit<30, 30, 225, 225>(l5, 960, 27648000u, u - 4096, 0);
            __syncthreads();
            ur = s_u;
        }
    }
    gridbar(2 * NB);

    // ---- P3: per-channel tables ----
    if (blockIdx.x < 46 && threadIdx.x < 32) {
        int gc = blockIdx.x * 32 + threadIdx.x;
        if (gc < NCH) stats_ch(gc);
    }
    gridbar(3 * NB);

    // ---- P4: proc sums, work-stolen (439 uniform units) ----
    if (threadIdx.x == 0) s_u = (int)atomicAdd(&g_ctr[2], 1u);
    __syncthreads();
    {
        int u = s_u;
        while (u < 439) {
            __syncthreads();
            if (threadIdx.x == 0) s_u = (int)atomicAdd(&g_ctr[2], 1u);
            if (u < 225)       proc_unit<64, 480, 480, true>(0u, 0, 0, u, 0, sM, sZ);
            else if (u < 339) { int i = u - 225;
                                proc_unit<128, 240, 240, false>(14745600u, 230400, 64, i >> 1, i & 1, sM, sZ); }
            else if (u < 399) { int i = u - 339;
                                proc_unit<256, 120, 120, false>(22118400u, 288000, 192, i >> 2, i & 3, sM, sZ); }
            else if (u < 431) { int i = u - 399;
                                proc_unit<512, 60, 60, false>(25804800u, 302400, 448, i >> 3, i & 7, sM, sZ); }
            else              { int i = u - 431;
                                proc_unit<512, 30, 30, false>(27648000u, 306000, 960, 0, i, sM, sZ); }
            __syncthreads();
            u = s_u;
        }
    }
    gridbar(4 * NB);

    // ---- P5: all-layer pmin/pmax (76725 float4, 1/thread) ----
    {
        if (threadIdx.x < 5) { sred[threadIdx.x] = 0xffffffffu; sred[12 + threadIdx.x] = 0u; }
        __syncthreads();
        int tg = blockIdx.x * 256 + threadIdx.x;
        if (tg < 76725) {
            float4 v = ((const float4*)g_proc)[tg];
            int l = (tg < 57600) ? 0 : (tg < 72000) ? 1 : (tg < 75600) ? 2
                  : (tg < 76500) ? 3 : 4;
            float mn = fminf(fminf(v.x, v.y), fminf(v.z, v.w));
            float mx = fmaxf(fmaxf(v.x, v.y), fmaxf(v.z, v.w));
            atomicMin(&sred[l], fenc(mn));
            atomicMax(&sred[12 + l], fenc(mx));
        }
        __syncthreads();
        if (threadIdx.x < 5) {
            atomicMin(&g_pmin[threadIdx.x], sred[threadIdx.x]);
            atomicMax(&g_pmax[threadIdx.x], sred[12 + threadIdx.x]);
        }
    }
    gridbar(5 * NB);

    // ---- P6: resize, work-stolen (1125 units) ----
    if (threadIdx.x == 0) s_u = (int)atomicAdd(&g_ctr[3], 1u);
    __syncthreads();
    {
        int u = s_u;
        while (u < 1125) {
            __syncthreads();
            if (threadIdx.x == 0) s_u = (int)atomicAdd(&g_ctr[3], 1u);
            if (u < 225)      resize_unit<480>(u, 0, 0, sred, ssum);
            else if (u < 450) resize_unit<240>(u - 225, 230400, 1, sred, ssum);
            else if (u < 675) resize_unit<120>(u - 450, 288000, 2, sred, ssum);
            else if (u < 900) resize_unit<60>(u - 675, 302400, 3, sred, ssum);
            else              resize_unit<30>(u - 900, 306000, 4, sred, ssum);
            __syncthreads();
            u = s_u;
        }
    }
    gridbar(6 * NB);

    // ---- P7: final groups + sum ----
    if (blockIdx.x < 225) {
        int idx = blockIdx.x * 256 + threadIdx.x;
        float s = 0.f;
#pragma unroll
        for (int l = 0; l < 5; l++) {
            float v = g_resized[l * 57600 + idx];
            float rmn = fdec(g_rmin[l]);
            float rmx = fdec(g_rmax[l]);
            float rrng = rmx - rmn;
            float rmean = g_rsum[l] / 57600.f;
            float t = rmx - rmean;
            float w3 = t * t;
            float g = (rrng == 0.f || w3 == 0.f)
                      ? 0.f
                      : __fmul_rn(__fdiv_rn(__fsub_rn(v, rmn), rrng), 256.f);
            s += g;
            out[57600 + idx * 5 + l] = g;
        }
        out[idx] = s;
    }
}

extern "C" void kernel_launch(void* const* d_in, const int* in_sizes, int n_in,
                              void* d_out, int out_size) {
    const float* l1 = (const float*)d_in[0];
    const float* l2 = (const float*)d_in[1];
    const float* l3 = (const float*)d_in[2];
    const float* l4 = (const float*)d_in[3];
    const float* l5 = (const float*)d_in[4];
    float* out = (float*)d_out;

    k_init<<<300, 256>>>();
    k_main<<<NB, 256>>>(l1, l2, l3, l4, l5, out);
}

// round 10
// speedup vs baseline: 1.0344x; 1.0244x over previous
#include <cuda_runtime.h>
#include <cuda_bf16.h>
#include <math.h>
#include <float.h>
#include <stdint.h>

// ---------------------------------------------------------------------------
// DeepRare, persistent kernel. This round: P1/P2 loads restructured into
// explicit batch-of-4 float4 groups (load loop separated from use loop) to
// force MLP>=4 per warp -- prior profiles showed ptxas emitting load-use
// chains (MLP~1-2) capping streaming at ~3.2 TB/s.
// ---------------------------------------------------------------------------

#define NCH 1472
#define GIDX_TOTAL 28108800
#define NB 740          // 148 SMs x 5 blocks (fits 152-SM GB300 too)

__device__ unsigned g_bar;
__device__ unsigned g_ctr[4];
__device__ unsigned g_cmin[NCH], g_cmax[NCH];
__device__ unsigned g_hist[NCH][6], g_hist2[NCH][6];
__device__ float g_M[NCH][6], g_Z[NCH];
__device__ __align__(16) unsigned char g_gidx[GIDX_TOTAL];
__device__ __align__(16) float g_proc[306912];
__device__ unsigned g_pmin[5], g_pmax[5];
__device__ float g_resized[5 * 57600];
__device__ unsigned g_rmin[5], g_rmax[5];
__device__ float g_rsum[5];

__device__ __forceinline__ unsigned fenc(float f) {
    unsigned u = __float_as_uint(f);
    return (u & 0x80000000u) ? ~u : (u | 0x80000000u);
}
__device__ __forceinline__ float fdec(unsigned e) {
    return (e & 0x80000000u) ? __uint_as_float(e & 0x7fffffffu)
                             : __uint_as_float(~e);
}

__device__ __forceinline__ void gridbar(unsigned tgt) {
    __syncthreads();
    if (threadIdx.x == 0) {
        __threadfence();
        atomicAdd(&g_bar, 1u);
        volatile unsigned* p = &g_bar;
        while (*p < tgt) { __nanosleep(20); }
        __threadfence();
    }
    __syncthreads();
}

__global__ void k_init() {
    int i = blockIdx.x * 256 + threadIdx.x;
    if (i == 0) g_bar = 0u;
    if (i < 4) g_ctr[i] = 0u;
    if (i < NCH * 6) {
        ((unsigned*)g_hist)[i] = 0u;
        ((unsigned*)g_hist2)[i] = 0u;
    }
    if (i < NCH) { g_cmin[i] = 0xffffffffu; g_cmax[i] = 0u; }
    if (i < 76512) g_proc[230400 + i] = 0.f;   // l2..l5 (atomic-accumulated)
    if (i < 5) {
        g_pmin[i] = 0xffffffffu; g_pmax[i] = 0u;
        g_rmin[i] = 0xffffffffu; g_rmax[i] = 0u;
        g_rsum[i] = 0.f;
    }
}

// ---- masked float4 (borders -> 0) -----------------------------------------
template <int H, int W>
__device__ __forceinline__ void mask4(int fc, float4 v,
                                      float& v0, float& v1, float& v2, float& v3) {
    if constexpr (W % 4 == 0) {
        constexpr int W4 = W / 4;
        int row = fc / W4;
        int col = fc - row * W4;
        bool br = (row == 0) | (row == H - 1);
        v0 = (br | (col == 0))      ? 0.f : v.x;
        v1 = br                      ? 0.f : v.y;
        v2 = br                      ? 0.f : v.z;
        v3 = (br | (col == W4 - 1)) ? 0.f : v.w;
    } else {
        int e = fc * 4;
        int y0 = e / W, x0 = e - y0 * W;
        int y1 = (e+1) / W, x1 = (e+1) - y1 * W;
        int y2 = (e+2) / W, x2 = (e+2) - y2 * W;
        int y3 = (e+3) / W, x3 = (e+3) - y3 * W;
        v0 = ((y0==0)|(x0==0)|(y0==H-1)|(x0==W-1)) ? 0.f : v.x;
        v1 = ((y1==0)|(x1==0)|(y1==H-1)|(x1==W-1)) ? 0.f : v.y;
        v2 = ((y2==0)|(x2==0)|(y2==H-1)|(x2==W-1)) ? 0.f : v.z;
        v3 = ((y3==0)|(x3==0)|(y3==H-1)|(x3==W-1)) ? 0.f : v.w;
    }
}

// -------- P1 unit: min/max, batch-of-4 loads (forced MLP) ------------------
template <int H, int W, int SL, int CHF4>
__device__ __forceinline__ void mm_unit(const float* __restrict__ in,
                                        int choff, int c, int s) {
    constexpr int F4PT = (SL + 255) / 256;
    const float4* p4 = (const float4*)in + (size_t)c * CHF4 + (size_t)s * SL;
    const int fbase = s * SL;
    float mn = 0.f, mx = 0.f;   // 0 always present in channel (borders)
#pragma unroll
    for (int g0 = 0; g0 < F4PT; g0 += 4) {
        float4 r[4]; int fli[4];
        // load batch first (independent LDG.128s issued back-to-back)
#pragma unroll
        for (int t = 0; t < 4; t++) {
            if (g0 + t < F4PT) {
                int fl = (g0 + t) * 256 + threadIdx.x;
                fli[t] = (SL % 256 == 0) ? fl : min(fl, SL - 1);
                r[t] = p4[fli[t]];
            }
        }
        // then consume (duplicates from clamping cannot change min/max)
#pragma unroll
        for (int t = 0; t < 4; t++) {
            if (g0 + t < F4PT) {
                float v0, v1, v2, v3;
                mask4<H, W>(fbase + fli[t], r[t], v0, v1, v2, v3);
                mn = fminf(mn, fminf(fminf(v0, v1), fminf(v2, v3)));
                mx = fmaxf(mx, fmaxf(fmaxf(v0, v1), fmaxf(v2, v3)));
            }
        }
    }
    unsigned emn = __reduce_min_sync(0xffffffffu, fenc(mn));
    unsigned emx = __reduce_max_sync(0xffffffffu, fenc(mx));
    if ((threadIdx.x & 31) == 0) {
        atomicMin(&g_cmin[choff + c], emn);
        atomicMax(&g_cmax[choff + c], emx);
    }
}

// -------- P2 unit: dual 6-bin hist + gidx, batch-of-4 loads ----------------
// u6 = (v - mn) * 1536/rng; iu = floor(u6)
//   bin = clamp(iu>>8, 0, 5); g = clamp(iu-1, 0, 5)
// Counters: 32-bit, bins 0..4 in 5x6-bit fields; bin-5 spills into scratch
// bits 30..31 / overflows out; bin5 = nact - sum(f0..f4).
template <int H, int W, int SL, int CHF4>
__device__ __forceinline__ void hist_unit(const float* __restrict__ in,
                                          int choff, size_t gidxoff,
                                          int c, int s) {
    constexpr int F4PT = (SL + 255) / 256;
    const int gc = choff + c;
    const float4* p4 = (const float4*)in + (size_t)c * CHF4 + (size_t)s * SL;
    uchar4* go = (uchar4*)(g_gidx + gidxoff) + (size_t)c * CHF4 + (size_t)s * SL;
    const int fbase = s * SL;
    const float mn = fdec(g_cmin[gc]);
    const float mx = fdec(g_cmax[gc]);
    const float rng = mx - mn;
    float inv6, mn6;
    if (rng == 0.f) { inv6 = 0.f; mn6 = 0.f; }
    else { inv6 = __fdiv_rn(1536.f, rng); mn6 = __fmul_rn(-mn, inv6); }
    unsigned pk1 = 0u, pk2 = 0u, nact = 0u;
#pragma unroll
    for (int g0 = 0; g0 < F4PT; g0 += 4) {
        float4 r[4]; bool act[4]; int fl[4];
#pragma unroll
        for (int t = 0; t < 4; t++) {
            if (g0 + t < F4PT) {
                int f = (g0 + t) * 256 + threadIdx.x;
                act[t] = (SL % 256 == 0) || (f < SL);
                fl[t] = act[t] ? f : 0;
                r[t] = p4[fl[t]];
            }
        }
#pragma unroll
        for (int t = 0; t < 4; t++) {
            if (g0 + t < F4PT) {
                float vv[4];
                mask4<H, W>(fbase + fl[t], r[t], vv[0], vv[1], vv[2], vv[3]);
                unsigned gb[4]; unsigned a1 = 0u, a2 = 0u;
#pragma unroll
                for (int k = 0; k < 4; k++) {
                    float u6 = __fmaf_rn(vv[k], inv6, mn6);
                    int iu = (int)floorf(u6);
                    int bin = min(5, max(0, iu >> 8));
                    int g = min(5, max(0, iu - 1));
                    a1 += 1u << (bin * 6);
                    a2 += 1u << (g * 6);
                    gb[k] = (unsigned)g;
                }
                if (act[t]) {
                    pk1 += a1; pk2 += a2; nact += 4u;
                    go[fl[t]] = make_uchar4(gb[0], gb[1], gb[2], gb[3]);
                }
            }
        }
    }
    unsigned f1[6], f2[6], s1 = 0u, s2 = 0u;
#pragma unroll
    for (int b = 0; b < 5; b++) {
        f1[b] = (pk1 >> (b * 6)) & 63u; s1 += f1[b];
        f2[b] = (pk2 >> (b * 6)) & 63u; s2 += f2[b];
    }
    f1[5] = nact - s1; f2[5] = nact - s2;
#pragma unroll
    for (int b = 0; b < 6; b++) {
        f1[b] = __reduce_add_sync(0xffffffffu, f1[b]);
        f2[b] = __reduce_add_sync(0xffffffffu, f2[b]);
    }
    if ((threadIdx.x & 31) == 0) {
#pragma unroll
        for (int b = 0; b < 6; b++) {
            if (f1[b]) atomicAdd(&g_hist[gc][b], f1[b]);
            if (f2[b]) atomicAdd(&g_hist2[gc][b], f2[b]);
        }
    }
}

// -------- P3: closed-form per-channel tables -------------------------------
__device__ __forceinline__ void stats_ch(int gc) {
    int choff, H, W;
    if (gc < 64)       { choff = 0;   H = 480; W = 480; }
    else if (gc < 192) { choff = 64;  H = 240; W = 240; }
    else if (gc < 448) { choff = 192; H = 120; W = 120; }
    else if (gc < 960) { choff = 448; H = 60;  W = 60;  }
    else               { choff = 960; H = 30;  W = 30;  }
    const int c = gc - choff;
    const float Nf = (float)(H * W);
    const int Nb = 2 * (H + W) - 4;

    float mn = fdec(g_cmin[gc]), mx = fdec(g_cmax[gc]);
    float rng = mx - mn;

    float hl[6]; unsigned h2[6];
#pragma unroll
    for (int b = 0; b < 6; b++) {
        float pr = __fadd_rn(__fdiv_rn((float)g_hist[gc][b], Nf), 1e-4f);
        hl[b] = -logf(pr);
        h2[b] = g_hist2[gc][b];
    }
    float dmin = FLT_MAX, dmax = -FLT_MAX, s = 0.f;
#pragma unroll
    for (int b = 0; b < 6; b++) if (h2[b]) {
        dmin = fminf(dmin, hl[b]); dmax = fmaxf(dmax, hl[b]);
        s += (float)h2[b] * hl[b];
    }
    float drng = dmax - dmin;
    float L[6];
    if (drng == 0.f) {
#pragma unroll
        for (int b = 0; b < 6; b++) L[b] = 0.f;
    } else {
        float meann = (s / Nf - dmin) / drng;
        float t = 1.f - meann;
        float w1 = t * t;
#pragma unroll
        for (int b = 0; b < 6; b++) L[b] = (hl[b] - dmin) / drng * w1;
    }
    // border gidx: EXACTLY the P2 formula applied to v=0 (u6 = mn6)
    int gb = 0;
    if (rng != 0.f) {
        float inv6 = __fdiv_rn(1536.f, rng);
        float mn6 = __fmul_rn(-mn, inv6);
        int iu = (int)floorf(mn6);
        gb = min(5, max(0, iu - 1));
    }
    float mmin = FLT_MAX, mmax = -FLT_MAX, s2 = 0.f;
#pragma unroll
    for (int b = 0; b < 6; b++) {
        unsigned cnt = h2[b];
        if (c > 0 && b == gb) cnt -= (unsigned)Nb;
        if (cnt) {
            mmin = fminf(mmin, L[b]); mmax = fmaxf(mmax, L[b]);
            s2 += (float)cnt * L[b];
        }
    }
    if (c > 0) { mmin = fminf(mmin, 0.f); mmax = fmaxf(mmax, 0.f); }
    float mrng = mmax - mmin;
    if (mrng == 0.f) {
#pragma unroll
        for (int b = 0; b < 6; b++) g_M[gc][b] = 0.f;
        g_Z[gc] = 0.f;
    } else {
        float mmean = s2 / Nf;
        float t = mmax - mmean;
        float w2 = t * t;
#pragma unroll
        for (int b = 0; b < 6; b++) g_M[gc][b] = (L[b] - mmin) / mrng * w2;
        g_Z[gc] = (0.f - mmin) / mrng * w2;
    }
}

// -------- P4 unit: proc += sum of 64 channels of M[c][gidx] ----------------
template <int C, int H, int W, bool DIRECT>
__device__ __forceinline__ void proc_unit(size_t gidxoff, int procoff,
                                          int choff, int pxblk, int cslice,
                                          float* sM, float* sZ) {
    constexpr int CS = 64;
    constexpr int HW = H * W;
    constexpr int NQ = HW / 4;
    const int cbeg = cslice * CS;
    for (int i = threadIdx.x; i < CS * 6; i += 256)
        sM[i] = ((const float*)g_M)[(choff + cbeg) * 6 + i];
    if (threadIdx.x < CS) sZ[threadIdx.x] = g_Z[choff + cbeg + threadIdx.x];
    __syncthreads();

    int q = pxblk * 256 + threadIdx.x;
    bool act = q < NQ;
    bool bf0 = false, bf1 = false, bf2 = false, bf3 = false;
    if (act) {
        if constexpr (W % 4 == 0) {
            constexpr int W4 = W / 4;
            int row = q / W4, col = q - row * W4;
            bool br = (row == 0) | (row == H - 1);
            bf0 = br | (col == 0); bf1 = br; bf2 = br;
            bf3 = br | (col == W4 - 1);
        } else {
            int e = q * 4;
#pragma unroll
            for (int k = 0; k < 4; k++) {
                int y = (e + k) / W, x = (e + k) - y * W;
                bool bb = (y == 0) | (x == 0) | (y == H - 1) | (x == W - 1);
                if (k == 0) bf0 = bb; else if (k == 1) bf1 = bb;
                else if (k == 2) bf2 = bb; else bf3 = bb;
            }
        }
    }
    bool anyb = __any_sync(0xffffffffu, act && (bf0 | bf1 | bf2 | bf3));
    float a0 = 0.f, a1 = 0.f, a2 = 0.f, a3 = 0.f;
    if (act) {
        const uchar4* gp = (const uchar4*)(g_gidx + gidxoff) + q;
        if (!anyb) {
#pragma unroll 8
            for (int cc = 0; cc < CS; cc++) {
                uchar4 gv = gp[(size_t)(cbeg + cc) * NQ];
                const float* mc = sM + cc * 6;
                a0 += mc[gv.x]; a1 += mc[gv.y]; a2 += mc[gv.z]; a3 += mc[gv.w];
            }
        } else {
#pragma unroll 8
            for (int cc = 0; cc < CS; cc++) {
                uchar4 gv = gp[(size_t)(cbeg + cc) * NQ];
                const float* mc = sM + cc * 6;
                bool ch0 = (cbeg + cc) == 0;   // layer ch 0 keeps border
                float z = sZ[cc];
                a0 += (bf0 && !ch0) ? z : mc[gv.x];
                a1 += (bf1 && !ch0) ? z : mc[gv.y];
                a2 += (bf2 && !ch0) ? z : mc[gv.z];
                a3 += (bf3 && !ch0) ? z : mc[gv.w];
            }
        }
        if constexpr (DIRECT) {
            ((float4*)(g_proc + procoff))[q] = make_float4(a0, a1, a2, a3);
        } else {
            float* pp = g_proc + procoff + q * 4;
            atomicAdd(pp + 0, a0); atomicAdd(pp + 1, a1);
            atomicAdd(pp + 2, a2); atomicAdd(pp + 3, a3);
        }
    }
}

// -------- P6 unit: resize + fused normalize/threshold + r-stats ------------
template <int S>
__device__ __forceinline__ void resize_unit(int b, int procoff, int layer,
                                            unsigned* sred, float* ssum) {
    int idx = b * 256 + threadIdx.x;   // 57600 = 225*256 exact
    int oy = idx / 240, ox = idx - oy * 240;
    float pmn = fdec(g_pmin[layer]);
    float pmx = fdec(g_pmax[layer]);
    float prng = pmx - pmn;
    constexpr float inv = (float)S / 240.f;
    constexpr float ks = (S > 240) ? inv : 1.f;
    constexpr float iks = 1.f / ks;
    float fy = (oy + 0.5f) * inv - 0.5f;
    float fx = (ox + 0.5f) * inv - 0.5f;
    int y0 = max(0, (int)ceilf(fy - ks)), y1 = min(S - 1, (int)floorf(fy + ks));
    int x0 = max(0, (int)ceilf(fx - ks)), x1 = min(S - 1, (int)floorf(fx + ks));
    float wy[4], wx[4];
    float sy = 0.f, sx = 0.f;
#pragma unroll
    for (int j = 0; j < 4; j++) {
        int yy = y0 + j;
        float w = (yy <= y1) ? fmaxf(0.f, 1.f - fabsf(fy - (float)yy) * iks) : 0.f;
        wy[j] = w; sy += w;
        int xx = x0 + j;
        float v = (xx <= x1) ? fmaxf(0.f, 1.f - fabsf(fx - (float)xx) * iks) : 0.f;
        wx[j] = v; sx += v;
    }
#pragma unroll
    for (int j = 0; j < 4; j++) {
        wy[j] = __fdiv_rn(wy[j], sy);
        wx[j] = __fdiv_rn(wx[j], sx);
    }
    const float* p = g_proc + procoff;
    float acc = 0.f;
#pragma unroll
    for (int jy = 0; jy < 4; jy++) {
        if (y0 + jy > y1) break;
        const float* row = p + (y0 + jy) * S;
        float r = 0.f;
#pragma unroll
        for (int jx = 0; jx < 4; jx++) {
            if (x0 + jx > x1) break;
            float v = row[x0 + jx];
            float n = (prng == 0.f) ? 0.f : __fdiv_rn(__fsub_rn(v, pmn), prng);
            n = (n < 0.2f) ? 0.f : n;
            r += wx[jx] * n;
        }
        acc += wy[jy] * r;
    }
    g_resized[layer * 57600 + idx] = acc;

    unsigned* smn = sred; unsigned* smx = sred + 8;
    unsigned emn = __reduce_min_sync(0xffffffffu, fenc(acc));
    unsigned emx = __reduce_max_sync(0xffffffffu, fenc(acc));
    float wsum = acc;
#pragma unroll
    for (int o = 16; o; o >>= 1) wsum += __shfl_xor_sync(0xffffffffu, wsum, o);
    if ((threadIdx.x & 31) == 0) {
        int w = threadIdx.x >> 5;
        smn[w] = emn; smx[w] = emx; ssum[w] = wsum;
    }
    __syncthreads();
    if (threadIdx.x == 0) {
        unsigned a = smn[0], bb = smx[0]; float s = ssum[0];
#pragma unroll
        for (int w = 1; w < 8; w++) {
            a = min(a, smn[w]); bb = max(bb, smx[w]); s += ssum[w];
        }
        atomicMin(&g_rmin[layer], a);
        atomicMax(&g_rmax[layer], bb);
        atomicAdd(&g_rsum[layer], s);
    }
    __syncthreads();
}

// ---------------------------- the fused kernel -----------------------------
__global__ __launch_bounds__(256, 5) void k_main(
    const float* __restrict__ l1, const float* __restrict__ l2,
    const float* __restrict__ l3, const float* __restrict__ l4,
    const float* __restrict__ l5, float* __restrict__ out) {
    __shared__ float sM[64 * 6];
    __shared__ float sZ[64];
    __shared__ unsigned sred[24];
    __shared__ float ssum[8];
    __shared__ int s_u;

    // ---- P1: minmax, work-stolen (4608 units) ----
    if (threadIdx.x == 0) s_u = (int)atomicAdd(&g_ctr[0], 1u);
    __syncthreads();
    {
        int u = s_u;
        while (u < 4608) {
            __syncthreads();
            if (threadIdx.x == 0) s_u = (int)atomicAdd(&g_ctr[0], 1u);
            if (u < 2048)      mm_unit<480, 480, 1800, 57600>(l1, 0, u >> 5, u & 31);
            else if (u < 3072) mm_unit<240, 240, 1800, 14400>(l2, 64, (u - 2048) >> 3, (u - 2048) & 7);
            else if (u < 3584) mm_unit<120, 120, 1800, 3600>(l3, 192, (u - 3072) >> 1, (u - 3072) & 1);
            else if (u < 4096) mm_unit<60, 60, 900, 900>(l4, 448, u - 3584, 0);
            else               mm_unit<30, 30, 225, 225>(l5, 960, u - 4096, 0);
            __syncthreads();
            u = s_u;
        }
    }
    gridbar(1 * NB);

    // ---- P2: hist + gidx, reversed order (recent layers L2-hot) ----
    if (threadIdx.x == 0) s_u = (int)atomicAdd(&g_ctr[1], 1u);
    __syncthreads();
    {
        int ur = s_u;
        while (ur < 4608) {
            __syncthreads();
            if (threadIdx.x == 0) s_u = (int)atomicAdd(&g_ctr[1], 1u);
            int u = 4607 - ur;
            if (u < 2048)      hist_unit<480, 480, 1800, 57600>(l1, 0, 0u, u >> 5, u & 31);
            else if (u < 3072) hist_unit<240, 240, 1800, 14400>(l2, 64, 14745600u, (u - 2048) >> 3, (u - 2048) & 7);
            else if (u < 3584) hist_unit<120, 120, 1800, 3600>(l3, 192, 22118400u, (u - 3072) >> 1, (u - 3072) & 1);
            else if (u < 4096) hist_unit<60, 60, 900, 900>(l4, 448, 25804800u, u - 3584, 0);
            else               hist_unit<30, 30, 225, 225>(l5, 960, 27648000u, u - 4096, 0);
            __syncthreads();
            ur = s_u;
        }
    }
    gridbar(2 * NB);

    // ---- P3: per-channel tables ----
    if (blockIdx.x < 46 && threadIdx.x < 32) {
        int gc = blockIdx.x * 32 + threadIdx.x;
        if (gc < NCH) stats_ch(gc);
    }
    gridbar(3 * NB);

    // ---- P4: proc sums, work-stolen (439 uniform units) ----
    if (threadIdx.x == 0) s_u = (int)atomicAdd(&g_ctr[2], 1u);
    __syncthreads();
    {
        int u = s_u;
        while (u < 439) {
            __syncthreads();
            if (threadIdx.x == 0) s_u = (int)atomicAdd(&g_ctr[2], 1u);
            if (u < 225)       proc_unit<64, 480, 480, true>(0u, 0, 0, u, 0, sM, sZ);
            else if (u < 339) { int i = u - 225;
                                proc_unit<128, 240, 240, false>(14745600u, 230400, 64, i >> 1, i & 1, sM, sZ); }
            else if (u < 399) { int i = u - 339;
                                proc_unit<256, 120, 120, false>(22118400u, 288000, 192, i >> 2, i & 3, sM, sZ); }
            else if (u < 431) { int i = u - 399;
                                proc_unit<512, 60, 60, false>(25804800u, 302400, 448, i >> 3, i & 7, sM, sZ); }
            else              { int i = u - 431;
                                proc_unit<512, 30, 30, false>(27648000u, 306000, 960, 0, i, sM, sZ); }
            __syncthreads();
            u = s_u;
        }
    }
    gridbar(4 * NB);

    // ---- P5: all-layer pmin/pmax (76725 float4, 1/thread) ----
    {
        if (threadIdx.x < 5) { sred[threadIdx.x] = 0xffffffffu; sred[12 + threadIdx.x] = 0u; }
        __syncthreads();
        int tg = blockIdx.x * 256 + threadIdx.x;
        if (tg < 76725) {
            float4 v = ((const float4*)g_proc)[tg];
            int l = (tg < 57600) ? 0 : (tg < 72000) ? 1 : (tg < 75600) ? 2
                  : (tg < 76500) ? 3 : 4;
            float mn = fminf(fminf(v.x, v.y), fminf(v.z, v.w));
            float mx = fmaxf(fmaxf(v.x, v.y), fmaxf(v.z, v.w));
            atomicMin(&sred[l], fenc(mn));
            atomicMax(&sred[12 + l], fenc(mx));
        }
        __syncthreads();
        if (threadIdx.x < 5) {
            atomicMin(&g_pmin[threadIdx.x], sred[threadIdx.x]);
            atomicMax(&g_pmax[threadIdx.x], sred[12 + threadIdx.x]);
        }
    }
    gridbar(5 * NB);

    // ---- P6: resize, work-stolen (1125 units) ----
    if (threadIdx.x == 0) s_u = (int)atomicAdd(&g_ctr[3], 1u);
    __syncthreads();
    {
        int u = s_u;
        while (u < 1125) {
            __syncthreads();
            if (threadIdx.x == 0) s_u = (int)atomicAdd(&g_ctr[3], 1u);
            if (u < 225)      resize_unit<480>(u, 0, 0, sred, ssum);
            else if (u < 450) resize_unit<240>(u - 225, 230400, 1, sred, ssum);
            else if (u < 675) resize_unit<120>(u - 450, 288000, 2, sred, ssum);
            else if (u < 900) resize_unit<60>(u - 675, 302400, 3, sred, ssum);
            else              resize_unit<30>(u - 900, 306000, 4, sred, ssum);
            __syncthreads();
            u = s_u;
        }
    }
    gridbar(6 * NB);

    // ---- P7: final groups + sum ----
    if (blockIdx.x < 225) {
        int idx = blockIdx.x * 256 + threadIdx.x;
        float s = 0.f;
#pragma unroll
        for (int l = 0; l < 5; l++) {
            float v = g_resized[l * 57600 + idx];
            float rmn = fdec(g_rmin[l]);
            float rmx = fdec(g_rmax[l]);
            float rrng = rmx - rmn;
            float rmean = g_rsum[l] / 57600.f;
            float t = rmx - rmean;
            float w3 = t * t;
            float g = (rrng == 0.f || w3 == 0.f)
                      ? 0.f
                      : __fmul_rn(__fdiv_rn(__fsub_rn(v, rmn), rrng), 256.f);
            s += g;
            out[57600 + idx * 5 + l] = g;
        }
        out[idx] = s;
    }
}

extern "C" void kernel_launch(void* const* d_in, const int* in_sizes, int n_in,
                              void* d_out, int out_size) {
    const float* l1 = (const float*)d_in[0];
    const float* l2 = (const float*)d_in[1];
    const float* l3 = (const float*)d_in[2];
    const float* l4 = (const float*)d_in[3];
    const float* l5 = (const float*)d_in[4];
    float* out = (float*)d_out;

    k_init<<<300, 256>>>();
    k_main<<<NB, 256>>>(l1, l2, l3, l4, l5, out);
}

// round 11
// speedup vs baseline: 1.1373x; 1.0995x over previous
#include <cuda_runtime.h>
#include <cuda_bf16.h>
#include <math.h>
#include <float.h>
#include <stdint.h>

// ---------------------------------------------------------------------------
// DeepRare, persistent kernel. This round: P1/P2 use cp.async (LDGSTS) into
// double-buffered dynamic smem -- register-free MLP (~57.6KB in flight per
// block) to break the ~1.4 TB/s latency wall measured in R5-R10.
// ---------------------------------------------------------------------------

#define NCH 1472
#define GIDX_TOTAL 28108800
#define NB 444            // 148 SMs x 3 blocks, single wave (GB300 152 ok)
#define SLMAX 1800        // max unit size in float4 (28.8 KB)
#define DYNSMEM (2 * SLMAX * 16)

__device__ unsigned g_bar;
__device__ unsigned g_ctr[4];
__device__ unsigned g_cmin[NCH], g_cmax[NCH];
__device__ unsigned g_hist[NCH][6], g_hist2[NCH][6];
__device__ float g_M[NCH][6], g_Z[NCH];
__device__ __align__(16) unsigned char g_gidx[GIDX_TOTAL];
__device__ __align__(16) float g_proc[306912];
__device__ unsigned g_pmin[5], g_pmax[5];
__device__ float g_resized[5 * 57600];
__device__ unsigned g_rmin[5], g_rmax[5];
__device__ float g_rsum[5];

__device__ __forceinline__ unsigned fenc(float f) {
    unsigned u = __float_as_uint(f);
    return (u & 0x80000000u) ? ~u : (u | 0x80000000u);
}
__device__ __forceinline__ float fdec(unsigned e) {
    return (e & 0x80000000u) ? __uint_as_float(e & 0x7fffffffu)
                             : __uint_as_float(~e);
}

__device__ __forceinline__ void gridbar(unsigned tgt) {
    __syncthreads();
    if (threadIdx.x == 0) {
        __threadfence();
        atomicAdd(&g_bar, 1u);
        volatile unsigned* p = &g_bar;
        while (*p < tgt) { __nanosleep(20); }
        __threadfence();
    }
    __syncthreads();
}

// ---- cp.async primitives ---------------------------------------------------
__device__ __forceinline__ void cp16(uint32_t dst, const void* src) {
    asm volatile("cp.async.cg.shared.global [%0], [%1], 16;\n"
                 :: "r"(dst), "l"(src));
}
__device__ __forceinline__ void cp_commit() {
    asm volatile("cp.async.commit_group;\n");
}
template <int N>
__device__ __forceinline__ void cp_wait() {
    asm volatile("cp.async.wait_group %0;\n" :: "n"(N));
}

__global__ void k_init() {
    int i = blockIdx.x * 256 + threadIdx.x;
    if (i == 0) g_bar = 0u;
    if (i < 4) g_ctr[i] = 0u;
    if (i < NCH * 6) {
        ((unsigned*)g_hist)[i] = 0u;
        ((unsigned*)g_hist2)[i] = 0u;
    }
    if (i < NCH) { g_cmin[i] = 0xffffffffu; g_cmax[i] = 0u; }
    if (i < 76512) g_proc[230400 + i] = 0.f;   // l2..l5 (atomic-accumulated)
    if (i < 5) {
        g_pmin[i] = 0xffffffffu; g_pmax[i] = 0u;
        g_rmin[i] = 0xffffffffu; g_rmax[i] = 0u;
        g_rsum[i] = 0.f;
    }
}

// ---- masked float4 (borders -> 0) -------------------------------------------
template <int H, int W>
__device__ __forceinline__ void mask4(int fc, float4 v,
                                      float& v0, float& v1, float& v2, float& v3) {
    if constexpr (W % 4 == 0) {
        constexpr int W4 = W / 4;
        int row = fc / W4;
        int col = fc - row * W4;
        bool br = (row == 0) | (row == H - 1);
        v0 = (br | (col == 0))      ? 0.f : v.x;
        v1 = br                      ? 0.f : v.y;
        v2 = br                      ? 0.f : v.z;
        v3 = (br | (col == W4 - 1)) ? 0.f : v.w;
    } else {
        int e = fc * 4;
        int y0 = e / W, x0 = e - y0 * W;
        int y1 = (e+1) / W, x1 = (e+1) - y1 * W;
        int y2 = (e+2) / W, x2 = (e+2) - y2 * W;
        int y3 = (e+3) / W, x3 = (e+3) - y3 * W;
        v0 = ((y0==0)|(x0==0)|(y0==H-1)|(x0==W-1)) ? 0.f : v.x;
        v1 = ((y1==0)|(x1==0)|(y1==H-1)|(x1==W-1)) ? 0.f : v.y;
        v2 = ((y2==0)|(x2==0)|(y2==H-1)|(x2==W-1)) ? 0.f : v.z;
        v3 = ((y3==0)|(x3==0)|(y3==H-1)|(x3==W-1)) ? 0.f : v.w;
    }
}

// ---- unit geometry dispatch (shared by P1/P2) --------------------------------
// u<2048: l1 c=u>>5 s=u&31 SL=1800 CHF4=57600 | u<3072: l2 >>3 &7 1800 14400
// u<3584: l3 >>1 &1 1800 3600 | u<4096: l4 900 900 | else l5 225 225

template <int SL, int CHF4>
__device__ __forceinline__ void issue_unit(const float* __restrict__ in,
                                           int c, int s, uint32_t sbuf) {
    const float4* p4 = (const float4*)in + (size_t)c * CHF4 + (size_t)s * SL;
    constexpr int K = (SL + 255) / 256;
#pragma unroll
    for (int k = 0; k < K; k++) {
        int fl = k * 256 + threadIdx.x;
        if (SL % 256 == 0 || fl < SL) cp16(sbuf + fl * 16, p4 + fl);
    }
}

__device__ __forceinline__ void p12_issue(int u, uint32_t sbuf,
    const float* __restrict__ l1, const float* __restrict__ l2,
    const float* __restrict__ l3, const float* __restrict__ l4,
    const float* __restrict__ l5) {
    if (u < 2048)      issue_unit<1800, 57600>(l1, u >> 5, u & 31, sbuf);
    else if (u < 3072) issue_unit<1800, 14400>(l2, (u - 2048) >> 3, (u - 2048) & 7, sbuf);
    else if (u < 3584) issue_unit<1800, 3600>(l3, (u - 3072) >> 1, (u - 3072) & 1, sbuf);
    else if (u < 4096) issue_unit<900, 900>(l4, u - 3584, 0, sbuf);
    else               issue_unit<225, 225>(l5, u - 4096, 0, sbuf);
}

// -------- P1 process: min/max from smem chunk --------------------------------
template <int H, int W, int SL>
__device__ __forceinline__ void mm_process(const float4* __restrict__ sbuf,
                                           int choff, int c, int s) {
    const int fbase = s * SL;
    constexpr int K = (SL + 255) / 256;
    float mn = 0.f, mx = 0.f;   // 0 always present in channel (borders)
#pragma unroll
    for (int k = 0; k < K; k++) {
        int fl = k * 256 + threadIdx.x;
        if (SL % 256 == 0 || fl < SL) {
            float4 v = sbuf[fl];
            float v0, v1, v2, v3;
            mask4<H, W>(fbase + fl, v, v0, v1, v2, v3);
            mn = fminf(mn, fminf(fminf(v0, v1), fminf(v2, v3)));
            mx = fmaxf(mx, fmaxf(fmaxf(v0, v1), fmaxf(v2, v3)));
        }
    }
    unsigned emn = __reduce_min_sync(0xffffffffu, fenc(mn));
    unsigned emx = __reduce_max_sync(0xffffffffu, fenc(mx));
    if ((threadIdx.x & 31) == 0) {
        atomicMin(&g_cmin[choff + c], emn);
        atomicMax(&g_cmax[choff + c], emx);
    }
}

__device__ __forceinline__ void p1_process(int u, const float4* sbuf) {
    if (u < 2048)      mm_process<480, 480, 1800>(sbuf, 0, u >> 5, u & 31);
    else if (u < 3072) mm_process<240, 240, 1800>(sbuf, 64, (u - 2048) >> 3, (u - 2048) & 7);
    else if (u < 3584) mm_process<120, 120, 1800>(sbuf, 192, (u - 3072) >> 1, (u - 3072) & 1);
    else if (u < 4096) mm_process<60, 60, 900>(sbuf, 448, u - 3584, 0);
    else               mm_process<30, 30, 225>(sbuf, 960, u - 4096, 0);
}

// -------- P2 process: dual 6-bin hist + gidx from smem chunk ------------------
// u6 = (v - mn) * 1536/rng; iu = floor(u6)
//   bin = clamp(iu>>8, 0, 5); g = clamp(iu-1, 0, 5)
// Counters: 32-bit, bins 0..4 in 5x6-bit fields (<=32 adds/unit); bin-5 adds
// spill to scratch bits / overflow out; bin5 = nact - sum(f0..f4).
template <int H, int W, int SL, int CHF4>
__device__ __forceinline__ void hist_process(const float4* __restrict__ sbuf,
                                             int choff, size_t gidxoff,
                                             int c, int s) {
    const int gc = choff + c;
    uchar4* go = (uchar4*)(g_gidx + gidxoff) + (size_t)c * CHF4 + (size_t)s * SL;
    const int fbase = s * SL;
    constexpr int K = (SL + 255) / 256;
    const float mn = fdec(g_cmin[gc]);
    const float mx = fdec(g_cmax[gc]);
    const float rng = mx - mn;
    float inv6, mn6;
    if (rng == 0.f) { inv6 = 0.f; mn6 = 0.f; }
    else { inv6 = __fdiv_rn(1536.f, rng); mn6 = __fmul_rn(-mn, inv6); }
    unsigned pk1 = 0u, pk2 = 0u, nact = 0u;
#pragma unroll
    for (int k = 0; k < K; k++) {
        int fl = k * 256 + threadIdx.x;
        if (SL % 256 == 0 || fl < SL) {
            float4 v = sbuf[fl];
            float vv[4];
            mask4<H, W>(fbase + fl, v, vv[0], vv[1], vv[2], vv[3]);
            unsigned gb[4];
#pragma unroll
            for (int kk = 0; kk < 4; kk++) {
                float u6 = __fmaf_rn(vv[kk], inv6, mn6);
                int iu = (int)floorf(u6);
                int bin = min(5, max(0, iu >> 8));
                int g = min(5, max(0, iu - 1));
                pk1 += 1u << (bin * 6);
                pk2 += 1u << (g * 6);
                gb[kk] = (unsigned)g;
            }
            nact += 4u;
            go[fl] = make_uchar4(gb[0], gb[1], gb[2], gb[3]);
        }
    }
    unsigned f1[6], f2[6], s1 = 0u, s2 = 0u;
#pragma unroll
    for (int b = 0; b < 5; b++) {
        f1[b] = (pk1 >> (b * 6)) & 63u; s1 += f1[b];
        f2[b] = (pk2 >> (b * 6)) & 63u; s2 += f2[b];
    }
    f1[5] = nact - s1; f2[5] = nact - s2;
#pragma unroll
    for (int b = 0; b < 6; b++) {
        f1[b] = __reduce_add_sync(0xffffffffu, f1[b]);
        f2[b] = __reduce_add_sync(0xffffffffu, f2[b]);
    }
    if ((threadIdx.x & 31) == 0) {
#pragma unroll
        for (int b = 0; b < 6; b++) {
            if (f1[b]) atomicAdd(&g_hist[gc][b], f1[b]);
            if (f2[b]) atomicAdd(&g_hist2[gc][b], f2[b]);
        }
    }
}

__device__ __forceinline__ void p2_process(int u, const float4* sbuf) {
    if (u < 2048)      hist_process<480, 480, 1800, 57600>(sbuf, 0, 0u, u >> 5, u & 31);
    else if (u < 3072) hist_process<240, 240, 1800, 14400>(sbuf, 64, 14745600u, (u - 2048) >> 3, (u - 2048) & 7);
    else if (u < 3584) hist_process<120, 120, 1800, 3600>(sbuf, 192, 22118400u, (u - 3072) >> 1, (u - 3072) & 1);
    else if (u < 4096) hist_process<60, 60, 900, 900>(sbuf, 448, 25804800u, u - 3584, 0);
    else               hist_process<30, 30, 225, 225>(sbuf, 960, 27648000u, u - 4096, 0);
}

// -------- P3: closed-form per-channel tables ---------------------------------
__device__ __forceinline__ void stats_ch(int gc) {
    int choff, H, W;
    if (gc < 64)       { choff = 0;   H = 480; W = 480; }
    else if (gc < 192) { choff = 64;  H = 240; W = 240; }
    else if (gc < 448) { choff = 192; H = 120; W = 120; }
    else if (gc < 960) { choff = 448; H = 60;  W = 60;  }
    else               { choff = 960; H = 30;  W = 30;  }
    const int c = gc - choff;
    const float Nf = (float)(H * W);
    const int Nb = 2 * (H + W) - 4;

    float mn = fdec(g_cmin[gc]), mx = fdec(g_cmax[gc]);
    float rng = mx - mn;

    float hl[6]; unsigned h2[6];
#pragma unroll
    for (int b = 0; b < 6; b++) {
        float pr = __fadd_rn(__fdiv_rn((float)g_hist[gc][b], Nf), 1e-4f);
        hl[b] = -logf(pr);
        h2[b] = g_hist2[gc][b];
    }
    float dmin = FLT_MAX, dmax = -FLT_MAX, s = 0.f;
#pragma unroll
    for (int b = 0; b < 6; b++) if (h2[b]) {
        dmin = fminf(dmin, hl[b]); dmax = fmaxf(dmax, hl[b]);
        s += (float)h2[b] * hl[b];
    }
    float drng = dmax - dmin;
    float L[6];
    if (drng == 0.f) {
#pragma unroll
        for (int b = 0; b < 6; b++) L[b] = 0.f;
    } else {
        float meann = (s / Nf - dmin) / drng;
        float t = 1.f - meann;
        float w1 = t * t;
#pragma unroll
        for (int b = 0; b < 6; b++) L[b] = (hl[b] - dmin) / drng * w1;
    }
    // border gidx: EXACTLY the P2 formula applied to v=0 (u6 = mn6)
    int gb = 0;
    if (rng != 0.f) {
        float inv6 = __fdiv_rn(1536.f, rng);
        float mn6 = __fmul_rn(-mn, inv6);
        int iu = (int)floorf(mn6);
        gb = min(5, max(0, iu - 1));
    }
    float mmin = FLT_MAX, mmax = -FLT_MAX, s2 = 0.f;
#pragma unroll
    for (int b = 0; b < 6; b++) {
        unsigned cnt = h2[b];
        if (c > 0 && b == gb) cnt -= (unsigned)Nb;
        if (cnt) {
            mmin = fminf(mmin, L[b]); mmax = fmaxf(mmax, L[b]);
            s2 += (float)cnt * L[b];
        }
    }
    if (c > 0) { mmin = fminf(mmin, 0.f); mmax = fmaxf(mmax, 0.f); }
    float mrng = mmax - mmin;
    if (mrng == 0.f) {
#pragma unroll
        for (int b = 0; b < 6; b++) g_M[gc][b] = 0.f;
        g_Z[gc] = 0.f;
    } else {
        float mmean = s2 / Nf;
        float t = mmax - mmean;
        float w2 = t * t;
#pragma unroll
        for (int b = 0; b < 6; b++) g_M[gc][b] = (L[b] - mmin) / mrng * w2;
        g_Z[gc] = (0.f - mmin) / mrng * w2;
    }
}

// -------- P4 unit: proc += sum of 64 channels of M[c][gidx] -------------------
template <int C, int H, int W, bool DIRECT>
__device__ __forceinline__ void proc_unit(size_t gidxoff, int procoff,
                                          int choff, int pxblk, int cslice,
                                          float* sM, float* sZ) {
    constexpr int CS = 64;
    constexpr int HW = H * W;
    constexpr int NQ = HW / 4;
    const int cbeg = cslice * CS;
    for (int i = threadIdx.x; i < CS * 6; i += 256)
        sM[i] = ((const float*)g_M)[(choff + cbeg) * 6 + i];
    if (threadIdx.x < CS) sZ[threadIdx.x] = g_Z[choff + cbeg + threadIdx.x];
    __syncthreads();

    int q = pxblk * 256 + threadIdx.x;
    bool act = q < NQ;
    bool bf0 = false, bf1 = false, bf2 = false, bf3 = false;
    if (act) {
        if constexpr (W % 4 == 0) {
            constexpr int W4 = W / 4;
            int row = q / W4, col = q - row * W4;
            bool br = (row == 0) | (row == H - 1);
            bf0 = br | (col == 0); bf1 = br; bf2 = br;
            bf3 = br | (col == W4 - 1);
        } else {
            int e = q * 4;
#pragma unroll
            for (int k = 0; k < 4; k++) {
                int y = (e + k) / W, x = (e + k) - y * W;
                bool bb = (y == 0) | (x == 0) | (y == H - 1) | (x == W - 1);
                if (k == 0) bf0 = bb; else if (k == 1) bf1 = bb;
                else if (k == 2) bf2 = bb; else bf3 = bb;
            }
        }
    }
    bool anyb = __any_sync(0xffffffffu, act && (bf0 | bf1 | bf2 | bf3));
    float a0 = 0.f, a1 = 0.f, a2 = 0.f, a3 = 0.f;
    if (act) {
        const uchar4* gp = (const uchar4*)(g_gidx + gidxoff) + q;
        if (!anyb) {
#pragma unroll 8
            for (int cc = 0; cc < CS; cc++) {
                uchar4 gv = gp[(size_t)(cbeg + cc) * NQ];
                const float* mc = sM + cc * 6;
                a0 += mc[gv.x]; a1 += mc[gv.y]; a2 += mc[gv.z]; a3 += mc[gv.w];
            }
        } else {
#pragma unroll 8
            for (int cc = 0; cc < CS; cc++) {
                uchar4 gv = gp[(size_t)(cbeg + cc) * NQ];
                const float* mc = sM + cc * 6;
                bool ch0 = (cbeg + cc) == 0;   // layer ch 0 keeps border
                float z = sZ[cc];
                a0 += (bf0 && !ch0) ? z : mc[gv.x];
                a1 += (bf1 && !ch0) ? z : mc[gv.y];
                a2 += (bf2 && !ch0) ? z : mc[gv.z];
                a3 += (bf3 && !ch0) ? z : mc[gv.w];
            }
        }
        if constexpr (DIRECT) {
            ((float4*)(g_proc + procoff))[q] = make_float4(a0, a1, a2, a3);
        } else {
            float* pp = g_proc + procoff + q * 4;
            atomicAdd(pp + 0, a0); atomicAdd(pp + 1, a1);
            atomicAdd(pp + 2, a2); atomicAdd(pp + 3, a3);
        }
    }
    __syncthreads();
}

// -------- P6 unit: resize + fused normalize/threshold + r-stats ---------------
template <int S>
__device__ __forceinline__ void resize_unit(int b, int procoff, int layer,
                                            unsigned* sred, float* ssum) {
    int idx = b * 256 + threadIdx.x;   // 57600 = 225*256 exact
    int oy = idx / 240, ox = idx - oy * 240;
    float pmn = fdec(g_pmin[layer]);
    float pmx = fdec(g_pmax[layer]);
    float prng = pmx - pmn;
    constexpr float inv = (float)S / 240.f;
    constexpr float ks = (S > 240) ? inv : 1.f;
    constexpr float iks = 1.f / ks;
    float fy = (oy + 0.5f) * inv - 0.5f;
    float fx = (ox + 0.5f) * inv - 0.5f;
    int y0 = max(0, (int)ceilf(fy - ks)), y1 = min(S - 1, (int)floorf(fy + ks));
    int x0 = max(0, (int)ceilf(fx - ks)), x1 = min(S - 1, (int)floorf(fx + ks));
    float wy[4], wx[4];
    float sy = 0.f, sx = 0.f;
#pragma unroll
    for (int j = 0; j < 4; j++) {
        int yy = y0 + j;
        float w = (yy <= y1) ? fmaxf(0.f, 1.f - fabsf(fy - (float)yy) * iks) : 0.f;
        wy[j] = w; sy += w;
        int xx = x0 + j;
        float v = (xx <= x1) ? fmaxf(0.f, 1.f - fabsf(fx - (float)xx) * iks) : 0.f;
        wx[j] = v; sx += v;
    }
#pragma unroll
    for (int j = 0; j < 4; j++) {
        wy[j] = __fdiv_rn(wy[j], sy);
        wx[j] = __fdiv_rn(wx[j], sx);
    }
    const float* p = g_proc + procoff;
    float acc = 0.f;
#pragma unroll
    for (int jy = 0; jy < 4; jy++) {
        if (y0 + jy > y1) break;
        const float* row = p + (y0 + jy) * S;
        float r = 0.f;
#pragma unroll
        for (int jx = 0; jx < 4; jx++) {
            if (x0 + jx > x1) break;
            float v = row[x0 + jx];
            float n = (prng == 0.f) ? 0.f : __fdiv_rn(__fsub_rn(v, pmn), prng);
            n = (n < 0.2f) ? 0.f : n;
            r += wx[jx] * n;
        }
        acc += wy[jy] * r;
    }
    g_resized[layer * 57600 + idx] = acc;

    unsigned* smn = sred; unsigned* smx = sred + 8;
    unsigned emn = __reduce_min_sync(0xffffffffu, fenc(acc));
    unsigned emx = __reduce_max_sync(0xffffffffu, fenc(acc));
    float wsum = acc;
#pragma unroll
    for (int o = 16; o; o >>= 1) wsum += __shfl_xor_sync(0xffffffffu, wsum, o);
    if ((threadIdx.x & 31) == 0) {
        int w = threadIdx.x >> 5;
        smn[w] = emn; smx[w] = emx; ssum[w] = wsum;
    }
    __syncthreads();
    if (threadIdx.x == 0) {
        unsigned a = smn[0], bb = smx[0]; float s = ssum[0];
#pragma unroll
        for (int w = 1; w < 8; w++) {
            a = min(a, smn[w]); bb = max(bb, smx[w]); s += ssum[w];
        }
        atomicMin(&g_rmin[layer], a);
        atomicMax(&g_rmax[layer], bb);
        atomicAdd(&g_rsum[layer], s);
    }
    __syncthreads();
}

// ---------------------------- the fused kernel --------------------------------
__global__ __launch_bounds__(256, 3) void k_main(
    const float* __restrict__ l1, const float* __restrict__ l2,
    const float* __restrict__ l3, const float* __restrict__ l4,
    const float* __restrict__ l5, float* __restrict__ out) {
    extern __shared__ __align__(16) unsigned char dynbuf[];
    const float4* sbp[2] = { (const float4*)dynbuf,
                             (const float4*)(dynbuf + SLMAX * 16) };
    uint32_t sba[2];
    sba[0] = (uint32_t)__cvta_generic_to_shared(dynbuf);
    sba[1] = sba[0] + SLMAX * 16;

    __shared__ float sM[64 * 6];
    __shared__ float sZ[64];
    __shared__ unsigned sred[24];
    __shared__ float ssum[8];
    __shared__ int s_u;

    // ---- grab helper (inline) ----
#define GRAB(ci) ({ __syncthreads(); \
    if (threadIdx.x == 0) s_u = (int)atomicAdd(&g_ctr[ci], 1u); \
    __syncthreads(); s_u; })

    // ---- P1: minmax, cp.async double-buffered work stealing (4608 units) ----
    {
        int cur = GRAB(0);
        if (cur < 4608) p12_issue(cur, sba[0], l1, l2, l3, l4, l5);
        cp_commit();
        int nxt = (cur < 4608) ? GRAB(0) : 4608;
        if (nxt < 4608) p12_issue(nxt, sba[1], l1, l2, l3, l4, l5);
        cp_commit();
        int pb = 0;
        while (cur < 4608) {
            cp_wait<1>();
            p1_process(cur, sbp[pb]);
            cur = nxt; pb ^= 1;
            nxt = (cur < 4608) ? GRAB(0) : 4608;
            if (nxt < 4608) p12_issue(nxt, sba[pb ^ 1], l1, l2, l3, l4, l5);
            cp_commit();
        }
        cp_wait<0>();
    }
    gridbar(1 * NB);

    // ---- P2: hist + gidx, reversed order (recent layers L2-hot) ----
    {
        int ur = GRAB(1);
        int cur = (ur < 4608) ? (4607 - ur) : -1;
        if (cur >= 0) p12_issue(cur, sba[0], l1, l2, l3, l4, l5);
        cp_commit();
        int ur2 = (cur >= 0) ? GRAB(1) : 4608;
        int nxt = (ur2 < 4608) ? (4607 - ur2) : -1;
        if (nxt >= 0) p12_issue(nxt, sba[1], l1, l2, l3, l4, l5);
        cp_commit();
        int pb = 0;
        while (cur >= 0) {
            cp_wait<1>();
            p2_process(cur, sbp[pb]);
            cur = nxt; pb ^= 1;
            if (cur >= 0) {
                int ur3 = GRAB(1);
                nxt = (ur3 < 4608) ? (4607 - ur3) : -1;
                if (nxt >= 0) p12_issue(nxt, sba[pb ^ 1], l1, l2, l3, l4, l5);
            }
            cp_commit();
        }
        cp_wait<0>();
    }
    gridbar(2 * NB);

    // ---- P3: per-channel tables ----
    if (blockIdx.x < 46 && threadIdx.x < 32) {
        int gc = blockIdx.x * 32 + threadIdx.x;
        if (gc < NCH) stats_ch(gc);
    }
    gridbar(3 * NB);

    // ---- P4: proc sums, work-stolen (439 uniform units) ----
    {
        int u = GRAB(2);
        while (u < 439) {
            if (u < 225)       proc_unit<64, 480, 480, true>(0u, 0, 0, u, 0, sM, sZ);
            else if (u < 339) { int i = u - 225;
                                proc_unit<128, 240, 240, false>(14745600u, 230400, 64, i >> 1, i & 1, sM, sZ); }
            else if (u < 399) { int i = u - 339;
                                proc_unit<256, 120, 120, false>(22118400u, 288000, 192, i >> 2, i & 3, sM, sZ); }
            else if (u < 431) { int i = u - 399;
                                proc_unit<512, 60, 60, false>(25804800u, 302400, 448, i >> 3, i & 7, sM, sZ); }
            else              { int i = u - 431;
                                proc_unit<512, 30, 30, false>(27648000u, 306000, 960, 0, i, sM, sZ); }
            u = GRAB(2);
        }
    }
    gridbar(4 * NB);

    // ---- P5: all-layer pmin/pmax (76725 float4, 1/thread) ----
    {
        if (threadIdx.x < 5) { sred[threadIdx.x] = 0xffffffffu; sred[12 + threadIdx.x] = 0u; }
        __syncthreads();
        int tg = blockIdx.x * 256 + threadIdx.x;
        if (tg < 76725) {
            float4 v = ((const float4*)g_proc)[tg];
            int l = (tg < 57600) ? 0 : (tg < 72000) ? 1 : (tg < 75600) ? 2
                  : (tg < 76500) ? 3 : 4;
            float mn = fminf(fminf(v.x, v.y), fminf(v.z, v.w));
            float mx = fmaxf(fmaxf(v.x, v.y), fmaxf(v.z, v.w));
            atomicMin(&sred[l], fenc(mn));
            atomicMax(&sred[12 + l], fenc(mx));
        }
        __syncthreads();
        if (threadIdx.x < 5) {
            atomicMin(&g_pmin[threadIdx.x], sred[threadIdx.x]);
            atomicMax(&g_pmax[threadIdx.x], sred[12 + threadIdx.x]);
        }
    }
    gridbar(5 * NB);

    // ---- P6: resize, work-stolen (1125 units) ----
    {
        int u = GRAB(3);
        while (u < 1125) {
            if (u < 225)      resize_unit<480>(u, 0, 0, sred, ssum);
            else if (u < 450) resize_unit<240>(u - 225, 230400, 1, sred, ssum);
            else if (u < 675) resize_unit<120>(u - 450, 288000, 2, sred, ssum);
            else if (u < 900) resize_unit<60>(u - 675, 302400, 3, sred, ssum);
            else              resize_unit<30>(u - 900, 306000, 4, sred, ssum);
            u = GRAB(3);
        }
    }
    gridbar(6 * NB);

    // ---- P7: final groups + sum ----
    if (blockIdx.x < 225) {
        int idx = blockIdx.x * 256 + threadIdx.x;
        float s = 0.f;
#pragma unroll
        for (int l = 0; l < 5; l++) {
            float v = g_resized[l * 57600 + idx];
            float rmn = fdec(g_rmin[l]);
            float rmx = fdec(g_rmax[l]);
            float rrng = rmx - rmn;
            float rmean = g_rsum[l] / 57600.f;
            float t = rmx - rmean;
            float w3 = t * t;
            float g = (rrng == 0.f || w3 == 0.f)
                      ? 0.f
                      : __fmul_rn(__fdiv_rn(__fsub_rn(v, rmn), rrng), 256.f);
            s += g;
            out[57600 + idx * 5 + l] = g;
        }
        out[idx] = s;
    }
#undef GRAB
}

extern "C" void kernel_launch(void* const* d_in, const int* in_sizes, int n_in,
                              void* d_out, int out_size) {
    const float* l1 = (const float*)d_in[0];
    const float* l2 = (const float*)d_in[1];
    const float* l3 = (const float*)d_in[2];
    const float* l4 = (const float*)d_in[3];
    const float* l5 = (const float*)d_in[4];
    float* out = (float*)d_out;

    cudaFuncSetAttribute(k_main, cudaFuncAttributeMaxDynamicSharedMemorySize,
                         DYNSMEM);
    k_init<<<300, 256>>>();
    k_main<<<NB, 256, DYNSMEM>>>(l1, l2, l3, l4, l5, out);
}